// round 1
// baseline (speedup 1.0000x reference)
#include <cuda_runtime.h>

#define B 128
#define S 400
#define H 256
#define E 128
#define V 50000
#define PAD 250
#define VP 50250
#define H2 512
#define H3 768

// Output layout: concat of flattened (h_new, p_final, p_gen, p_vocab, att_dist)
#define OUT_HNEW   0
#define OUT_PFINAL (B*H)
#define OUT_PGEN   (OUT_PFINAL + B*VP)
#define OUT_PVOCAB (OUT_PGEN + B)
#define OUT_ATT    (OUT_PVOCAB + B*V)

#define SMEM_D1 ((E*B + 64*129)*4)

// ---------------- scratch (static device globals; no allocation) -------------
__device__ float g_x[B*E];
__device__ float g_hnew[B*H];
__device__ float g_gsum[B*H3];
__device__ float g_ghn[B*H];
__device__ float g_scores[B*S];
__device__ float g_ad[B*S];
__device__ float g_decHT[E*B];      // [e][b] transposed for the vocab GEMM
__device__ float g_logits[B*V];     // 25.6 MB
__device__ float g_rowmax[B];
__device__ float g_rowinv[B];
__device__ float g_pgen[B];

// ---------------- A0: embedding gather ---------------------------------------
__global__ void k_embed(const int* __restrict__ tok, const float* __restrict__ emb) {
    int b = blockIdx.x;
    int t = tok[b];
    g_x[b*E + threadIdx.x] = emb[(size_t)t*E + threadIdx.x];
}

// ---------------- A1: GRU gate GEMMs (gi + gh fused; h_n kept separate) ------
// gsum[b][j] = (x@Wih^T)[j] + (h@Whh^T)[j] + bih[j] + bhh[j]
// ghn [b][j-512] = (h@Whh^T)[j] + bhh[j]   for j in [512,768)
__global__ __launch_bounds__(256) void k_gates(
    const float* __restrict__ hprev, const float* __restrict__ Wih,
    const float* __restrict__ Whh,  const float* __restrict__ bih,
    const float* __restrict__ bhh) {
    __shared__ float xhT[384*20];   // [k][b_loc], padded
    __shared__ float wT[64*65];     // [kk][j_loc], padded
    int j0 = blockIdx.x*64, b0 = blockIdx.y*16;
    int tid = threadIdx.x;

    for (int i = tid; i < 16*384; i += 256) {
        int bl = i/384, k = i%384;
        float v = (k < 128) ? g_x[(b0+bl)*E + k] : hprev[(b0+bl)*H + (k-128)];
        xhT[k*20 + bl] = v;
    }

    int j_loc = tid & 63, bq = tid >> 6;
    int j = j0 + j_loc;
    bool isN = (j >= 2*H);
    float acc[4]  = {0.f,0.f,0.f,0.f};
    float accn[4] = {0.f,0.f,0.f,0.f};

    for (int kt = 0; kt < 384; kt += 64) {
        __syncthreads();
        for (int i = tid; i < 64*64; i += 256) {
            int jl = i >> 6, kk = i & 63;
            int k = kt + kk, jj = j0 + jl;
            float w = (k < 128) ? Wih[(size_t)jj*E + k] : Whh[(size_t)jj*H + (k-128)];
            wT[kk*65 + jl] = w;
        }
        __syncthreads();
        if (kt < 128) {
            #pragma unroll 8
            for (int kk = 0; kk < 64; kk++) {
                float w = wT[kk*65 + j_loc];
                float4 xv = *(const float4*)&xhT[(kt+kk)*20 + bq*4];
                acc[0] = fmaf(w, xv.x, acc[0]); acc[1] = fmaf(w, xv.y, acc[1]);
                acc[2] = fmaf(w, xv.z, acc[2]); acc[3] = fmaf(w, xv.w, acc[3]);
            }
        } else {
            #pragma unroll 8
            for (int kk = 0; kk < 64; kk++) {
                float w = wT[kk*65 + j_loc];
                float4 xv = *(const float4*)&xhT[(kt+kk)*20 + bq*4];
                acc[0] = fmaf(w, xv.x, acc[0]); acc[1] = fmaf(w, xv.y, acc[1]);
                acc[2] = fmaf(w, xv.z, acc[2]); acc[3] = fmaf(w, xv.w, acc[3]);
                accn[0] = fmaf(w, xv.x, accn[0]); accn[1] = fmaf(w, xv.y, accn[1]);
                accn[2] = fmaf(w, xv.z, accn[2]); accn[3] = fmaf(w, xv.w, accn[3]);
            }
        }
    }
    float bs = bih[j] + bhh[j];
    #pragma unroll
    for (int i = 0; i < 4; i++) {
        int b = b0 + bq*4 + i;
        g_gsum[b*H3 + j] = acc[i] + bs;
        if (isN) g_ghn[b*H + (j - 2*H)] = accn[i] + bhh[j];
    }
}

// ---------------- A2: GRU elementwise ----------------------------------------
__global__ void k_gru(const float* __restrict__ hprev, float* __restrict__ out) {
    int b = blockIdx.x, j = threadIdx.x;
    float gr = g_gsum[b*H3 + j];
    float gz = g_gsum[b*H3 + H + j];
    float gn = g_gsum[b*H3 + 2*H + j];
    float hn = g_ghn[b*H + j];
    float r = 1.f/(1.f + __expf(-gr));
    float z = 1.f/(1.f + __expf(-gz));
    float n = tanhf(gn + (r - 1.f)*hn);   // i_n + r*h_n == gsum + (r-1)*h_n
    float h = (1.f - z)*n + z*hprev[b*H + j];
    g_hnew[b*H + j] = h;
    out[OUT_HNEW + b*H + j] = h;
}

// ---------------- B: attention scores (streams 52MB of enc) ------------------
__global__ __launch_bounds__(256) void k_scores(
    const float* __restrict__ enc, const float* __restrict__ wh,
    const float* __restrict__ ws,  const float* __restrict__ ab,
    const float* __restrict__ av) {
    __shared__ float s_wh[H], s_av[H], s_ch[H];
    int b = blockIdx.y, tid = threadIdx.x;
    s_wh[tid] = wh[tid];
    s_av[tid] = av[tid];
    s_ch[tid] = fmaf(ws[tid], g_hnew[b*H + tid], ab[0]);
    __syncthreads();

    int warp = tid >> 5, lane = tid & 31;
    int s = blockIdx.x*8 + warp;
    const float* ep = enc + ((size_t)b*S + s)*H;
    float acc = 0.f;
    #pragma unroll
    for (int r = 0; r < 8; r++) {
        int h = lane + r*32;
        float e = ep[h];
        acc = fmaf(tanhf(fmaf(s_wh[h], e, s_ch[h])), s_av[h], acc);
    }
    #pragma unroll
    for (int o = 16; o; o >>= 1) acc += __shfl_xor_sync(0xffffffffu, acc, o);
    if (lane == 0) g_scores[b*S + s] = acc;
}

// ---------------- C: softmax(S) + context + dec_h + p_gen (per batch row) ----
__global__ __launch_bounds__(256) void k_attn(
    const float* __restrict__ enc,  const float* __restrict__ outhw,
    const float* __restrict__ outhb, const float* __restrict__ genw,
    const float* __restrict__ genb,  float* __restrict__ out) {
    __shared__ float ad[S];
    __shared__ float dctx[2*H];
    __shared__ float red[256];
    int b = blockIdx.x, tid = threadIdx.x;

    float lm = -1e30f;
    for (int i = tid; i < S; i += 256) { float v = g_scores[b*S + i]; ad[i] = v; lm = fmaxf(lm, v); }
    red[tid] = lm; __syncthreads();
    for (int o = 128; o; o >>= 1) { if (tid < o) red[tid] = fmaxf(red[tid], red[tid+o]); __syncthreads(); }
    float mx = red[0];
    __syncthreads();
    float ls = 0.f;
    for (int i = tid; i < S; i += 256) { float e = __expf(ad[i] - mx); ad[i] = e; ls += e; }
    red[tid] = ls; __syncthreads();
    for (int o = 128; o; o >>= 1) { if (tid < o) red[tid] += red[tid+o]; __syncthreads(); }
    float inv = 1.f/red[0];
    __syncthreads();
    for (int i = tid; i < S; i += 256) {
        float a = ad[i]*inv; ad[i] = a;
        g_ad[b*S + i] = a;
        out[OUT_ATT + b*S + i] = a;
    }
    dctx[tid] = g_hnew[b*H + tid];
    __syncthreads();

    // context[h] = sum_s ad[s]*enc[b,s,h]  (enc hot in L2 from kernel B)
    {
        const float* ep = enc + (size_t)b*S*H + tid;
        float c = 0.f;
        #pragma unroll 4
        for (int s = 0; s < S; s++) c = fmaf(ad[s], ep[(size_t)s*H], c);
        dctx[H + tid] = c;
    }
    __syncthreads();

    // dec_h[e] = outh_b[e] + dctx . outh_w[e,:], stored transposed [e][b]
    int warp = tid >> 5, lane = tid & 31;
    for (int e0 = 0; e0 < 16; e0++) {
        int e = warp*16 + e0;
        const float* wr = outhw + (size_t)e*H2;
        float a = 0.f;
        #pragma unroll
        for (int i = 0; i < 16; i++) a = fmaf(wr[lane + i*32], dctx[lane + i*32], a);
        #pragma unroll
        for (int o = 16; o; o >>= 1) a += __shfl_xor_sync(0xffffffffu, a, o);
        if (lane == 0) g_decHT[e*B + b] = a + outhb[e];
    }

    // p_gen = sigmoid([dctx, x] . gen_w + gen_b)
    float p = 0.f;
    for (int i = tid; i < 2*H + E; i += 256) {
        float cv = (i < 2*H) ? dctx[i] : g_x[b*E + (i - 2*H)];
        p = fmaf(cv, genw[i], p);
    }
    red[tid] = p; __syncthreads();
    for (int o = 128; o; o >>= 1) { if (tid < o) red[tid] += red[tid+o]; __syncthreads(); }
    if (tid == 0) {
        float pg = 1.f/(1.f + __expf(-(red[0] + genb[0])));
        g_pgen[b] = pg;
        out[OUT_PGEN + b] = pg;
    }
}

// ---------------- D1: vocab GEMM  logits[b,v] = dec_h[b,:].outv_w[v,:]+bv ----
// 64 vocab rows x all 128 batch per block; 4x8 register micro-tile per thread.
extern __shared__ float smem_d1[];
__global__ __launch_bounds__(256, 2) void k_logits(
    const float* __restrict__ Wv, const float* __restrict__ bv) {
    float* dh = smem_d1;            // [k=128][b=128]
    float* wS = smem_d1 + E*B;      // [v=64][k], padded to 129
    int v0 = blockIdx.x*64;
    int tid = threadIdx.x;

    {   // dec_h already stored [e][b]: straight float4 copy
        const float4* src = (const float4*)g_decHT;
        float4* dst = (float4*)dh;
        for (int i = tid; i < E*B/4; i += 256) dst[i] = src[i];
    }
    for (int i = tid; i < 64*128; i += 256) {
        int vl = i >> 7, k = i & 127;
        int v = v0 + vl;
        wS[vl*129 + k] = (v < V) ? Wv[(size_t)v*E + k] : 0.f;
    }
    __syncthreads();

    int vq = tid & 15, bq = tid >> 4;      // v: vq + 16*i ; b: bq*8 + j
    float acc[4][8];
    #pragma unroll
    for (int i = 0; i < 4; i++)
        #pragma unroll
        for (int j = 0; j < 8; j++) acc[i][j] = 0.f;

    const float* wp = wS + vq*129;
    const float* dp = dh + bq*8;
    #pragma unroll 4
    for (int k = 0; k < E; k++) {
        float w0 = wp[k];
        float w1 = wp[16*129 + k];
        float w2 = wp[32*129 + k];
        float w3 = wp[48*129 + k];
        float4 d0 = *(const float4*)&dp[k*B];
        float4 d1 = *(const float4*)&dp[k*B + 4];
        float dv[8] = {d0.x,d0.y,d0.z,d0.w,d1.x,d1.y,d1.z,d1.w};
        #pragma unroll
        for (int j = 0; j < 8; j++) {
            acc[0][j] = fmaf(w0, dv[j], acc[0][j]);
            acc[1][j] = fmaf(w1, dv[j], acc[1][j]);
            acc[2][j] = fmaf(w2, dv[j], acc[2][j]);
            acc[3][j] = fmaf(w3, dv[j], acc[3][j]);
        }
    }
    #pragma unroll
    for (int i = 0; i < 4; i++) {
        int v = v0 + vq + i*16;
        if (v < V) {
            float bias = bv[v];
            #pragma unroll
            for (int j = 0; j < 8; j++) {
                int b = bq*8 + j;
                g_logits[(size_t)b*V + v] = acc[i][j] + bias;
            }
        }
    }
}

// ---------------- D2: per-row online softmax stats over V --------------------
__global__ void k_smax() {
    int b = blockIdx.x, tid = threadIdx.x;
    const float* lp = g_logits + (size_t)b*V;
    float m = -1e30f, s = 0.f;
    for (int v = tid; v < V; v += 256) {
        float l = lp[v];
        if (l > m) { s = s*__expf(m - l) + 1.f; m = l; }
        else        s += __expf(l - m);
    }
    __shared__ float sm[256], ss[256];
    sm[tid] = m; ss[tid] = s; __syncthreads();
    for (int o = 128; o; o >>= 1) {
        if (tid < o) {
            float m1 = sm[tid], s1 = ss[tid];
            float m2 = sm[tid+o], s2 = ss[tid+o];
            float nm = fmaxf(m1, m2);
            sm[tid] = nm;
            ss[tid] = s1*__expf(m1 - nm) + s2*__expf(m2 - nm);
        }
        __syncthreads();
    }
    if (tid == 0) { g_rowmax[b] = sm[0]; g_rowinv[b] = 1.f/ss[0]; }
}

// ---------------- E: p_vocab + p_final (dense part + PAD zeros) --------------
__global__ void k_final(float* __restrict__ out) {
    int b = blockIdx.y;
    int v = blockIdx.x*256 + threadIdx.x;
    float pg = g_pgen[b];
    if (v < V) {
        float l = g_logits[(size_t)b*V + v];
        float pv = __expf(l - g_rowmax[b]) * g_rowinv[b];
        out[OUT_PVOCAB + (size_t)b*V + v] = pv;
        out[OUT_PFINAL + (size_t)b*VP + v] = pv*pg;
    } else if (v < VP) {
        out[OUT_PFINAL + (size_t)b*VP + v] = 0.f;
    }
}

// ---------------- F: pointer scatter into p_final ----------------------------
__global__ void k_scatter(const int* __restrict__ fiv, float* __restrict__ out) {
    int b = blockIdx.x;
    float w = 1.f - g_pgen[b];
    for (int s = threadIdx.x; s < S; s += blockDim.x) {
        int idx = fiv[b*S + s];
        atomicAdd(&out[OUT_PFINAL + (size_t)b*VP + idx], w*g_ad[b*S + s]);
    }
}

// ---------------- launcher ---------------------------------------------------
extern "C" void kernel_launch(void* const* d_in, const int* in_sizes, int n_in,
                              void* d_out, int out_size) {
    const int*   tok   = (const int*)  d_in[0];
    const float* hprev = (const float*)d_in[1];
    const float* enc   = (const float*)d_in[2];
    const int*   fiv   = (const int*)  d_in[3];
    const float* emb   = (const float*)d_in[4];
    const float* Wih   = (const float*)d_in[5];
    const float* Whh   = (const float*)d_in[6];
    const float* bih   = (const float*)d_in[7];
    const float* bhh   = (const float*)d_in[8];
    const float* wh    = (const float*)d_in[9];
    const float* ws    = (const float*)d_in[10];
    const float* ab    = (const float*)d_in[11];
    const float* av    = (const float*)d_in[12];
    const float* genw  = (const float*)d_in[13];
    const float* genb  = (const float*)d_in[14];
    const float* outhw = (const float*)d_in[15];
    const float* outhb = (const float*)d_in[16];
    const float* Wv    = (const float*)d_in[17];
    const float* bv    = (const float*)d_in[18];
    float* out = (float*)d_out;

    cudaFuncSetAttribute(k_logits, cudaFuncAttributeMaxDynamicSharedMemorySize, SMEM_D1);

    k_embed  <<<B, E>>>(tok, emb);
    k_gates  <<<dim3(12, 8), 256>>>(hprev, Wih, Whh, bih, bhh);
    k_gru    <<<B, H>>>(hprev, out);
    k_scores <<<dim3(S/8, B), 256>>>(enc, wh, ws, ab, av);
    k_attn   <<<B, 256>>>(enc, outhw, outhb, genw, genb, out);
    k_logits <<<(V + 63)/64, 256, SMEM_D1>>>(Wv, bv);
    k_smax   <<<B, 256>>>();
    k_final  <<<dim3((VP + 255)/256, B), 256>>>(out);
    k_scatter<<<B, 256>>>(fiv, out);
}

// round 2
// speedup vs baseline: 1.0651x; 1.0651x over previous
#include <cuda_runtime.h>
#include <cuda_bf16.h>
#include <cstdint>

#define B 128
#define S 400
#define H 256
#define E 128
#define V 50000
#define PAD 250
#define VP 50250
#define H2 512
#define H3 768
#define NBLK 391            // ceil(V/128)
#define WSTR 136            // bf16 elems per smem row (bank-conflict-free ldmatrix)
#define VSTR 132            // floats per staged C row

// Output layout: concat of flattened (h_new, p_final, p_gen, p_vocab, att_dist)
#define OUT_HNEW   0
#define OUT_PFINAL (B*H)
#define OUT_PGEN   (OUT_PFINAL + B*VP)
#define OUT_PVOCAB (OUT_PGEN + B)
#define OUT_ATT    (OUT_PVOCAB + B*V)

#define SMEM_D1 (4*128*WSTR*2 + 128*4)   // 4 bf16 tiles + bias row

// ---------------- scratch (static device globals; no allocation) -------------
__device__ float g_x[B*E];
__device__ float g_hnew[B*H];
__device__ float g_gsum[B*H3];
__device__ float g_ghn[B*H];
__device__ float g_scores[B*S];
__device__ float g_ad[B*S];
__device__ float g_decH[B*E];        // [b][e] fp32
__device__ float g_logits[B*V];      // 25.6 MB
__device__ float g_pmax[B*NBLK];
__device__ float g_psum[B*NBLK];
__device__ float g_rowmax[B];
__device__ float g_rowinv[B];
__device__ float g_pgen[B];

__device__ __forceinline__ float fast_tanh(float x) {
    float t = __expf(-2.f*fabsf(x));
    float r = __fdividef(1.f - t, 1.f + t);
    return copysignf(r, x);
}

__device__ __forceinline__ uint32_t smem_u32(const void* p) {
    return (uint32_t)__cvta_generic_to_shared(p);
}

// ---------------- A0: embedding gather ---------------------------------------
__global__ void k_embed(const int* __restrict__ tok, const float* __restrict__ emb) {
    int b = blockIdx.x;
    int t = tok[b];
    g_x[b*E + threadIdx.x] = emb[(size_t)t*E + threadIdx.x];
}

// ---------------- A1: GRU gate GEMMs ------------------------------------------
__global__ __launch_bounds__(256) void k_gates(
    const float* __restrict__ hprev, const float* __restrict__ Wih,
    const float* __restrict__ Whh,  const float* __restrict__ bih,
    const float* __restrict__ bhh) {
    __shared__ float xhT[384*20];
    __shared__ float wT[64*65];
    int j0 = blockIdx.x*64, b0 = blockIdx.y*16;
    int tid = threadIdx.x;

    for (int i = tid; i < 16*384; i += 256) {
        int bl = i/384, k = i%384;
        float v = (k < 128) ? g_x[(b0+bl)*E + k] : hprev[(b0+bl)*H + (k-128)];
        xhT[k*20 + bl] = v;
    }

    int j_loc = tid & 63, bq = tid >> 6;
    int j = j0 + j_loc;
    bool isN = (j >= 2*H);
    float acc[4]  = {0.f,0.f,0.f,0.f};
    float accn[4] = {0.f,0.f,0.f,0.f};

    for (int kt = 0; kt < 384; kt += 64) {
        __syncthreads();
        for (int i = tid; i < 64*64; i += 256) {
            int jl = i >> 6, kk = i & 63;
            int k = kt + kk, jj = j0 + jl;
            float w = (k < 128) ? Wih[(size_t)jj*E + k] : Whh[(size_t)jj*H + (k-128)];
            wT[kk*65 + jl] = w;
        }
        __syncthreads();
        if (kt < 128) {
            #pragma unroll 8
            for (int kk = 0; kk < 64; kk++) {
                float w = wT[kk*65 + j_loc];
                float4 xv = *(const float4*)&xhT[(kt+kk)*20 + bq*4];
                acc[0] = fmaf(w, xv.x, acc[0]); acc[1] = fmaf(w, xv.y, acc[1]);
                acc[2] = fmaf(w, xv.z, acc[2]); acc[3] = fmaf(w, xv.w, acc[3]);
            }
        } else {
            #pragma unroll 8
            for (int kk = 0; kk < 64; kk++) {
                float w = wT[kk*65 + j_loc];
                float4 xv = *(const float4*)&xhT[(kt+kk)*20 + bq*4];
                acc[0] = fmaf(w, xv.x, acc[0]); acc[1] = fmaf(w, xv.y, acc[1]);
                acc[2] = fmaf(w, xv.z, acc[2]); acc[3] = fmaf(w, xv.w, acc[3]);
                accn[0] = fmaf(w, xv.x, accn[0]); accn[1] = fmaf(w, xv.y, accn[1]);
                accn[2] = fmaf(w, xv.z, accn[2]); accn[3] = fmaf(w, xv.w, accn[3]);
            }
        }
    }
    float bs = bih[j] + bhh[j];
    #pragma unroll
    for (int i = 0; i < 4; i++) {
        int b = b0 + bq*4 + i;
        g_gsum[b*H3 + j] = acc[i] + bs;
        if (isN) g_ghn[b*H + (j - 2*H)] = accn[i] + bhh[j];
    }
}

// ---------------- A2: GRU elementwise ----------------------------------------
__global__ void k_gru(const float* __restrict__ hprev, float* __restrict__ out) {
    int b = blockIdx.x, j = threadIdx.x;
    float gr = g_gsum[b*H3 + j];
    float gz = g_gsum[b*H3 + H + j];
    float gn = g_gsum[b*H3 + 2*H + j];
    float hn = g_ghn[b*H + j];
    float r = 1.f/(1.f + __expf(-gr));
    float z = 1.f/(1.f + __expf(-gz));
    float n = tanhf(gn + (r - 1.f)*hn);
    float h = (1.f - z)*n + z*hprev[b*H + j];
    g_hnew[b*H + j] = h;
    out[OUT_HNEW + b*H + j] = h;
}

// ---------------- B: attention scores ----------------------------------------
__global__ __launch_bounds__(256) void k_scores(
    const float* __restrict__ enc, const float* __restrict__ wh,
    const float* __restrict__ ws,  const float* __restrict__ ab,
    const float* __restrict__ av) {
    __shared__ float s_wh[H], s_av[H], s_ch[H];
    int b = blockIdx.y, tid = threadIdx.x;
    s_wh[tid] = wh[tid];
    s_av[tid] = av[tid];
    s_ch[tid] = fmaf(ws[tid], g_hnew[b*H + tid], ab[0]);
    __syncthreads();

    int warp = tid >> 5, lane = tid & 31;
    int s = blockIdx.x*8 + warp;
    const float* ep = enc + ((size_t)b*S + s)*H;
    float acc = 0.f;
    #pragma unroll
    for (int r = 0; r < 8; r++) {
        int h = lane + r*32;
        float e = ep[h];
        acc = fmaf(fast_tanh(fmaf(s_wh[h], e, s_ch[h])), s_av[h], acc);
    }
    #pragma unroll
    for (int o = 16; o; o >>= 1) acc += __shfl_xor_sync(0xffffffffu, acc, o);
    if (lane == 0) g_scores[b*S + s] = acc;
}

// ---------------- C: softmax(S) + context + dec_h + p_gen --------------------
__global__ __launch_bounds__(256) void k_attn(
    const float* __restrict__ enc,  const float* __restrict__ outhw,
    const float* __restrict__ outhb, const float* __restrict__ genw,
    const float* __restrict__ genb,  float* __restrict__ out) {
    __shared__ float ad[S];
    __shared__ float dctx[2*H];
    __shared__ float red[256];
    int b = blockIdx.x, tid = threadIdx.x;

    float lm = -1e30f;
    for (int i = tid; i < S; i += 256) { float v = g_scores[b*S + i]; ad[i] = v; lm = fmaxf(lm, v); }
    red[tid] = lm; __syncthreads();
    for (int o = 128; o; o >>= 1) { if (tid < o) red[tid] = fmaxf(red[tid], red[tid+o]); __syncthreads(); }
    float mx = red[0];
    __syncthreads();
    float ls = 0.f;
    for (int i = tid; i < S; i += 256) { float e = __expf(ad[i] - mx); ad[i] = e; ls += e; }
    red[tid] = ls; __syncthreads();
    for (int o = 128; o; o >>= 1) { if (tid < o) red[tid] += red[tid+o]; __syncthreads(); }
    float inv = 1.f/red[0];
    __syncthreads();
    for (int i = tid; i < S; i += 256) {
        float a = ad[i]*inv; ad[i] = a;
        g_ad[b*S + i] = a;
        out[OUT_ATT + b*S + i] = a;
    }
    dctx[tid] = g_hnew[b*H + tid];
    __syncthreads();

    {
        const float* ep = enc + (size_t)b*S*H + tid;
        float c = 0.f;
        #pragma unroll 4
        for (int s = 0; s < S; s++) c = fmaf(ad[s], ep[(size_t)s*H], c);
        dctx[H + tid] = c;
    }
    __syncthreads();

    int warp = tid >> 5, lane = tid & 31;
    for (int e0 = 0; e0 < 16; e0++) {
        int e = warp*16 + e0;
        const float* wr = outhw + (size_t)e*H2;
        float a = 0.f;
        #pragma unroll
        for (int i = 0; i < 16; i++) a = fmaf(wr[lane + i*32], dctx[lane + i*32], a);
        #pragma unroll
        for (int o = 16; o; o >>= 1) a += __shfl_xor_sync(0xffffffffu, a, o);
        if (lane == 0) g_decH[b*E + e] = a + outhb[e];
    }

    float p = 0.f;
    for (int i = tid; i < 2*H + E; i += 256) {
        float cv = (i < 2*H) ? dctx[i] : g_x[b*E + (i - 2*H)];
        p = fmaf(cv, genw[i], p);
    }
    red[tid] = p; __syncthreads();
    for (int o = 128; o; o >>= 1) { if (tid < o) red[tid] += red[tid+o]; __syncthreads(); }
    if (tid == 0) {
        float pg = 1.f/(1.f + __expf(-(red[0] + genb[0])));
        g_pgen[b] = pg;
        out[OUT_PGEN + b] = pg;
    }
}

// ---------------- D: vocab GEMM via bf16 tensor-core 3-pass split -------------
// logits[b,v] = dec_h[b,:] . Wv[v,:] + bv[v], computed as
//   Wh*Dh + Wh*Dl + Wl*Dh  (Wl*Dl ~ 2^-16, dropped)
// block: 128 vocab x 128 batch.  warp tile: 32 vocab x 64 batch (8 warps).
extern __shared__ char smem_d[];
__global__ __launch_bounds__(256, 1) void k_logits(
    const float* __restrict__ Wv, const float* __restrict__ bv) {
    __nv_bfloat16* sWh = (__nv_bfloat16*)smem_d;
    __nv_bfloat16* sWl = sWh + 128*WSTR;
    __nv_bfloat16* sDh = sWl + 128*WSTR;
    __nv_bfloat16* sDl = sDh + 128*WSTR;
    float* sC    = (float*)smem_d;                    // reused after MMA passes
    float* sBias = (float*)(smem_d + 4*128*WSTR*2);

    int tid = threadIdx.x;
    int v0 = blockIdx.x*128;

    // load + split W tile (zero-pad past V)
    for (int i = tid; i < 128*128; i += 256) {
        int r = i >> 7, k = i & 127;
        int v = v0 + r;
        float w = (v < V) ? Wv[(size_t)v*E + k] : 0.f;
        __nv_bfloat16 hh = __float2bfloat16(w);
        sWh[r*WSTR + k] = hh;
        sWl[r*WSTR + k] = __float2bfloat16(w - __bfloat162float(hh));
    }
    // load + split dec_h (L2-resident, 64KB)
    for (int i = tid; i < 128*128; i += 256) {
        int bb = i >> 7, k = i & 127;
        float d = g_decH[bb*E + k];
        __nv_bfloat16 hh = __float2bfloat16(d);
        sDh[bb*WSTR + k] = hh;
        sDl[bb*WSTR + k] = __float2bfloat16(d - __bfloat162float(hh));
    }
    if (tid < 128) sBias[tid] = (v0 + tid < V) ? bv[v0 + tid] : 0.f;
    __syncthreads();

    int warp = tid >> 5, lane = tid & 31;
    int mBase = (warp & 3)*32;     // vocab offset in tile
    int nBase = (warp >> 2)*64;    // batch offset in tile

    float acc[2][8][4];
    #pragma unroll
    for (int mi = 0; mi < 2; mi++)
        #pragma unroll
        for (int j = 0; j < 8; j++)
            #pragma unroll
            for (int q = 0; q < 4; q++) acc[mi][j][q] = 0.f;

    // ldmatrix per-thread element offsets (in elements)
    int aRow = mBase + (lane & 7) + ((lane >> 3) & 1)*8;
    int aK   = (lane >> 4)*8;
    int bRow = nBase + (lane & 7) + (lane >> 4)*8;
    int bK   = ((lane >> 3) & 1)*8;

    uint32_t uWh = smem_u32(sWh), uWl = smem_u32(sWl);
    uint32_t uDh = smem_u32(sDh), uDl = smem_u32(sDl);

    #pragma unroll 1
    for (int pass = 0; pass < 3; pass++) {
        uint32_t uA = (pass == 2) ? uWl : uWh;
        uint32_t uB = (pass == 1) ? uDl : uDh;
        uint32_t aAddr0 = uA + (uint32_t)(aRow*WSTR + aK)*2;
        uint32_t bAddr0 = uB + (uint32_t)(bRow*WSTR + bK)*2;
        #pragma unroll
        for (int k0 = 0; k0 < 128; k0 += 16) {
            uint32_t a[2][4];
            #pragma unroll
            for (int mi = 0; mi < 2; mi++) {
                uint32_t ad2 = aAddr0 + (uint32_t)(mi*16*WSTR + k0)*2;
                asm volatile("ldmatrix.sync.aligned.m8n8.x4.shared.b16 {%0,%1,%2,%3}, [%4];"
                    : "=r"(a[mi][0]), "=r"(a[mi][1]), "=r"(a[mi][2]), "=r"(a[mi][3])
                    : "r"(ad2));
            }
            #pragma unroll
            for (int jp = 0; jp < 4; jp++) {
                uint32_t bfr[4];
                uint32_t bd = bAddr0 + (uint32_t)(jp*16*WSTR + k0)*2;
                asm volatile("ldmatrix.sync.aligned.m8n8.x4.shared.b16 {%0,%1,%2,%3}, [%4];"
                    : "=r"(bfr[0]), "=r"(bfr[1]), "=r"(bfr[2]), "=r"(bfr[3])
                    : "r"(bd));
                #pragma unroll
                for (int mi = 0; mi < 2; mi++) {
                    asm volatile(
                        "mma.sync.aligned.m16n8k16.row.col.f32.bf16.bf16.f32 "
                        "{%0,%1,%2,%3}, {%4,%5,%6,%7}, {%8,%9}, {%0,%1,%2,%3};"
                        : "+f"(acc[mi][2*jp][0]), "+f"(acc[mi][2*jp][1]),
                          "+f"(acc[mi][2*jp][2]), "+f"(acc[mi][2*jp][3])
                        : "r"(a[mi][0]), "r"(a[mi][1]), "r"(a[mi][2]), "r"(a[mi][3]),
                          "r"(bfr[0]), "r"(bfr[1]));
                    asm volatile(
                        "mma.sync.aligned.m16n8k16.row.col.f32.bf16.bf16.f32 "
                        "{%0,%1,%2,%3}, {%4,%5,%6,%7}, {%8,%9}, {%0,%1,%2,%3};"
                        : "+f"(acc[mi][2*jp+1][0]), "+f"(acc[mi][2*jp+1][1]),
                          "+f"(acc[mi][2*jp+1][2]), "+f"(acc[mi][2*jp+1][3])
                        : "r"(a[mi][0]), "r"(a[mi][1]), "r"(a[mi][2]), "r"(a[mi][3]),
                          "r"(bfr[2]), "r"(bfr[3]));
                }
            }
        }
    }

    // stage C into smem (transpose to [b][v]) — reuses W region
    __syncthreads();
    #pragma unroll
    for (int mi = 0; mi < 2; mi++)
        #pragma unroll
        for (int j = 0; j < 8; j++)
            #pragma unroll
            for (int q = 0; q < 4; q++) {
                int vl = mBase + 16*mi + (lane >> 2) + ((q >> 1) ? 8 : 0);
                int bl = nBase + 8*j + 2*(lane & 3) + (q & 1);
                sC[bl*VSTR + vl] = acc[mi][j][q];
            }
    __syncthreads();

    // per-b-row: add bias, write logits, softmax partials (max, sum of exp)
    int nvalid = min(128, V - v0);
    for (int r = 0; r < 16; r++) {
        int bb = warp*16 + r;
        const float4 x4 = ((const float4*)(sC + bb*VSTR))[lane];
        int vl = lane*4;
        float val[4] = {x4.x + sBias[vl], x4.y + sBias[vl+1],
                        x4.z + sBias[vl+2], x4.w + sBias[vl+3]};
        float m = -1e30f;
        #pragma unroll
        for (int i = 0; i < 4; i++) if (vl + i < nvalid) m = fmaxf(m, val[i]);
        #pragma unroll
        for (int o = 16; o; o >>= 1) m = fmaxf(m, __shfl_xor_sync(0xffffffffu, m, o));
        float s = 0.f;
        #pragma unroll
        for (int i = 0; i < 4; i++) if (vl + i < nvalid) s += __expf(val[i] - m);
        #pragma unroll
        for (int o = 16; o; o >>= 1) s += __shfl_xor_sync(0xffffffffu, s, o);
        #pragma unroll
        for (int i = 0; i < 4; i++)
            if (vl + i < nvalid) g_logits[(size_t)bb*V + v0 + vl + i] = val[i];
        if (lane == 0) {
            g_pmax[bb*NBLK + blockIdx.x] = m;
            g_psum[bb*NBLK + blockIdx.x] = s;
        }
    }
}

// ---------------- D2: combine softmax partials (tiny) ------------------------
__global__ void k_comb() {
    __shared__ float sm[128], ss[128];
    int b = blockIdx.x, tid = threadIdx.x;
    float m = -1e30f, s = 0.f;
    for (int i = tid; i < NBLK; i += 128) {
        float pm = g_pmax[b*NBLK + i], ps = g_psum[b*NBLK + i];
        if (pm > m) { s = s*__expf(m - pm) + ps; m = pm; }
        else          s += ps*__expf(pm - m);
    }
    sm[tid] = m; ss[tid] = s; __syncthreads();
    for (int o = 64; o; o >>= 1) {
        if (tid < o) {
            float m1 = sm[tid], s1 = ss[tid];
            float m2 = sm[tid+o], s2 = ss[tid+o];
            float nm = fmaxf(m1, m2);
            sm[tid] = nm;
            ss[tid] = s1*__expf(m1 - nm) + s2*__expf(m2 - nm);
        }
        __syncthreads();
    }
    if (tid == 0) { g_rowmax[b] = sm[0]; g_rowinv[b] = 1.f/ss[0]; }
}

// ---------------- E: p_vocab + p_final (vectorized) ---------------------------
__global__ __launch_bounds__(256) void k_final(float* __restrict__ out) {
    int b = blockIdx.y;
    int v = (blockIdx.x*256 + threadIdx.x)*4;
    if (v >= VP) return;
    float pg = g_pgen[b];
    if (v < V) {
        float4 l = *(const float4*)&g_logits[(size_t)b*V + v];
        float mx = g_rowmax[b], inv = g_rowinv[b];
        float4 p;
        p.x = __expf(l.x - mx)*inv; p.y = __expf(l.y - mx)*inv;
        p.z = __expf(l.z - mx)*inv; p.w = __expf(l.w - mx)*inv;
        *(float4*)&out[OUT_PVOCAB + (size_t)b*V + v] = p;
        float2 f0 = make_float2(p.x*pg, p.y*pg);
        float2 f1 = make_float2(p.z*pg, p.w*pg);
        *(float2*)&out[OUT_PFINAL + (size_t)b*VP + v]     = f0;
        *(float2*)&out[OUT_PFINAL + (size_t)b*VP + v + 2] = f1;
    } else {
        #pragma unroll
        for (int i = 0; i < 4; i += 2)
            if (v + i + 1 < VP + 1 && v + i < VP)
                *(float2*)&out[OUT_PFINAL + (size_t)b*VP + v + i] = make_float2(0.f, 0.f);
    }
}

// ---------------- F: pointer scatter ------------------------------------------
__global__ void k_scatter(const int* __restrict__ fiv, float* __restrict__ out) {
    int b = blockIdx.x;
    float w = 1.f - g_pgen[b];
    for (int s = threadIdx.x; s < S; s += blockDim.x) {
        int idx = fiv[b*S + s];
        atomicAdd(&out[OUT_PFINAL + (size_t)b*VP + idx], w*g_ad[b*S + s]);
    }
}

// ---------------- launcher ---------------------------------------------------
extern "C" void kernel_launch(void* const* d_in, const int* in_sizes, int n_in,
                              void* d_out, int out_size) {
    const int*   tok   = (const int*)  d_in[0];
    const float* hprev = (const float*)d_in[1];
    const float* enc   = (const float*)d_in[2];
    const int*   fiv   = (const int*)  d_in[3];
    const float* emb   = (const float*)d_in[4];
    const float* Wih   = (const float*)d_in[5];
    const float* Whh   = (const float*)d_in[6];
    const float* bih   = (const float*)d_in[7];
    const float* bhh   = (const float*)d_in[8];
    const float* wh    = (const float*)d_in[9];
    const float* ws    = (const float*)d_in[10];
    const float* ab    = (const float*)d_in[11];
    const float* av    = (const float*)d_in[12];
    const float* genw  = (const float*)d_in[13];
    const float* genb  = (const float*)d_in[14];
    const float* outhw = (const float*)d_in[15];
    const float* outhb = (const float*)d_in[16];
    const float* Wv    = (const float*)d_in[17];
    const float* bv    = (const float*)d_in[18];
    float* out = (float*)d_out;

    cudaFuncSetAttribute(k_logits, cudaFuncAttributeMaxDynamicSharedMemorySize, SMEM_D1);

    k_embed  <<<B, E>>>(tok, emb);
    k_gates  <<<dim3(12, 8), 256>>>(hprev, Wih, Whh, bih, bhh);
    k_gru    <<<B, H>>>(hprev, out);
    k_scores <<<dim3(S/8, B), 256>>>(enc, wh, ws, ab, av);
    k_attn   <<<B, 256>>>(enc, outhw, outhb, genw, genb, out);
    k_logits <<<NBLK, 256, SMEM_D1>>>(Wv, bv);
    k_comb   <<<B, 128>>>();
    k_final  <<<dim3((VP + 1023)/1024, B), 256>>>(out);
    k_scatter<<<B, 256>>>(fiv, out);
}

// round 3
// speedup vs baseline: 1.2767x; 1.1987x over previous
#include <cuda_runtime.h>
#include <cuda_bf16.h>
#include <cstdint>

#define B 128
#define S 400
#define H 256
#define E 128
#define V 50000
#define PAD 250
#define VP 50250
#define H2 512
#define H3 768
#define NBLK 391            // ceil(V/128)
#define WSTR 136            // bf16 elems per smem row (bank-conflict-free ldmatrix)
#define VSTR 132            // floats per staged C row

// Output layout: concat of flattened (h_new, p_final, p_gen, p_vocab, att_dist)
#define OUT_HNEW   0
#define OUT_PFINAL (B*H)
#define OUT_PGEN   (OUT_PFINAL + B*VP)
#define OUT_PVOCAB (OUT_PGEN + B)
#define OUT_ATT    (OUT_PVOCAB + B*V)

#define SMEM_D1 (3*128*WSTR*2 + 128*4)   // Wh, Wl, Dh bf16 tiles + bias row

// ---------------- scratch (static device globals; no allocation) -------------
__device__ float g_x[B*E];
__device__ float g_hnew[B*H];
__device__ float g_gsum[B*H3];
__device__ float g_ghn[B*H];
__device__ float g_scores[B*S];
__device__ float g_ad[B*S];
__device__ float g_decH[B*E];        // [b][e] fp32
__device__ float g_logits[B*V];      // 25.6 MB
__device__ float g_pmax[B*NBLK];
__device__ float g_psum[B*NBLK];
__device__ float g_rowmax[B];
__device__ float g_rowinv[B];
__device__ float g_pgen[B];

__device__ __forceinline__ float tanh_hw(float x) {
    float y;
    asm("tanh.approx.f32 %0, %1;" : "=f"(y) : "f"(x));
    return y;
}

__device__ __forceinline__ uint32_t smem_u32(const void* p) {
    return (uint32_t)__cvta_generic_to_shared(p);
}

// ---------------- A1: GRU gate GEMMs (embedding gather fused in) -------------
__global__ __launch_bounds__(256) void k_gates(
    const int* __restrict__ tok,    const float* __restrict__ emb,
    const float* __restrict__ hprev, const float* __restrict__ Wih,
    const float* __restrict__ Whh,  const float* __restrict__ bih,
    const float* __restrict__ bhh) {
    __shared__ float xhT[384*20];
    __shared__ float wT[64*65];
    __shared__ int   s_tok[16];
    int j0 = blockIdx.x*64, b0 = blockIdx.y*16;
    int tid = threadIdx.x;

    if (tid < 16) s_tok[tid] = tok[b0 + tid];
    __syncthreads();

    for (int i = tid; i < 16*384; i += 256) {
        int bl = i/384, k = i%384;
        float v = (k < 128) ? emb[(size_t)s_tok[bl]*E + k] : hprev[(b0+bl)*H + (k-128)];
        xhT[k*20 + bl] = v;
        if (blockIdx.x == 0 && k < 128) g_x[(b0+bl)*E + k] = v;
    }

    int j_loc = tid & 63, bq = tid >> 6;
    int j = j0 + j_loc;
    bool isN = (j >= 2*H);
    float acc[4]  = {0.f,0.f,0.f,0.f};
    float accn[4] = {0.f,0.f,0.f,0.f};

    for (int kt = 0; kt < 384; kt += 64) {
        __syncthreads();
        for (int i = tid; i < 64*64; i += 256) {
            int jl = i >> 6, kk = i & 63;
            int k = kt + kk, jj = j0 + jl;
            float w = (k < 128) ? Wih[(size_t)jj*E + k] : Whh[(size_t)jj*H + (k-128)];
            wT[kk*65 + jl] = w;
        }
        __syncthreads();
        if (kt < 128) {
            #pragma unroll 8
            for (int kk = 0; kk < 64; kk++) {
                float w = wT[kk*65 + j_loc];
                float4 xv = *(const float4*)&xhT[(kt+kk)*20 + bq*4];
                acc[0] = fmaf(w, xv.x, acc[0]); acc[1] = fmaf(w, xv.y, acc[1]);
                acc[2] = fmaf(w, xv.z, acc[2]); acc[3] = fmaf(w, xv.w, acc[3]);
            }
        } else {
            #pragma unroll 8
            for (int kk = 0; kk < 64; kk++) {
                float w = wT[kk*65 + j_loc];
                float4 xv = *(const float4*)&xhT[(kt+kk)*20 + bq*4];
                acc[0] = fmaf(w, xv.x, acc[0]); acc[1] = fmaf(w, xv.y, acc[1]);
                acc[2] = fmaf(w, xv.z, acc[2]); acc[3] = fmaf(w, xv.w, acc[3]);
                accn[0] = fmaf(w, xv.x, accn[0]); accn[1] = fmaf(w, xv.y, accn[1]);
                accn[2] = fmaf(w, xv.z, accn[2]); accn[3] = fmaf(w, xv.w, accn[3]);
            }
        }
    }
    float bs = bih[j] + bhh[j];
    #pragma unroll
    for (int i = 0; i < 4; i++) {
        int b = b0 + bq*4 + i;
        g_gsum[b*H3 + j] = acc[i] + bs;
        if (isN) g_ghn[b*H + (j - 2*H)] = accn[i] + bhh[j];
    }
}

// ---------------- A2: GRU elementwise (precise: h_new dominates out norm) ----
__global__ void k_gru(const float* __restrict__ hprev, float* __restrict__ out) {
    int b = blockIdx.x, j = threadIdx.x;
    float gr = g_gsum[b*H3 + j];
    float gz = g_gsum[b*H3 + H + j];
    float gn = g_gsum[b*H3 + 2*H + j];
    float hn = g_ghn[b*H + j];
    float r = 1.f/(1.f + __expf(-gr));
    float z = 1.f/(1.f + __expf(-gz));
    float n = tanhf(gn + (r - 1.f)*hn);
    float h = (1.f - z)*n + z*hprev[b*H + j];
    g_hnew[b*H + j] = h;
    out[OUT_HNEW + b*H + j] = h;
}

// ---------------- B: attention scores (tanh.approx + float4 loads) -----------
__global__ __launch_bounds__(256) void k_scores(
    const float* __restrict__ enc, const float* __restrict__ wh,
    const float* __restrict__ ws,  const float* __restrict__ ab,
    const float* __restrict__ av) {
    __shared__ float s_wh[H], s_av[H], s_ch[H];
    int b = blockIdx.y, tid = threadIdx.x;
    s_wh[tid] = wh[tid];
    s_av[tid] = av[tid];
    s_ch[tid] = fmaf(ws[tid], g_hnew[b*H + tid], ab[0]);
    __syncthreads();

    int warp = tid >> 5, lane = tid & 31;
    int s = blockIdx.x*8 + warp;
    const float* ep = enc + ((size_t)b*S + s)*H;
    int h0 = lane*4;
    float4 e0 = *(const float4*)&ep[h0];
    float4 e1 = *(const float4*)&ep[h0 + 128];
    float acc = 0.f;
    {
        const float4 w0 = *(const float4*)&s_wh[h0];
        const float4 c0 = *(const float4*)&s_ch[h0];
        const float4 a0 = *(const float4*)&s_av[h0];
        acc = fmaf(tanh_hw(fmaf(w0.x, e0.x, c0.x)), a0.x, acc);
        acc = fmaf(tanh_hw(fmaf(w0.y, e0.y, c0.y)), a0.y, acc);
        acc = fmaf(tanh_hw(fmaf(w0.z, e0.z, c0.z)), a0.z, acc);
        acc = fmaf(tanh_hw(fmaf(w0.w, e0.w, c0.w)), a0.w, acc);
        const float4 w1 = *(const float4*)&s_wh[h0 + 128];
        const float4 c1 = *(const float4*)&s_ch[h0 + 128];
        const float4 a1 = *(const float4*)&s_av[h0 + 128];
        acc = fmaf(tanh_hw(fmaf(w1.x, e1.x, c1.x)), a1.x, acc);
        acc = fmaf(tanh_hw(fmaf(w1.y, e1.y, c1.y)), a1.y, acc);
        acc = fmaf(tanh_hw(fmaf(w1.z, e1.z, c1.z)), a1.z, acc);
        acc = fmaf(tanh_hw(fmaf(w1.w, e1.w, c1.w)), a1.w, acc);
    }
    #pragma unroll
    for (int o = 16; o; o >>= 1) acc += __shfl_xor_sync(0xffffffffu, acc, o);
    if (lane == 0) g_scores[b*S + s] = acc;
}

// ---------------- C: softmax(S) + context + dec_h + p_gen --------------------
__global__ __launch_bounds__(256) void k_attn(
    const float* __restrict__ enc,  const float* __restrict__ outhw,
    const float* __restrict__ outhb, const float* __restrict__ genw,
    const float* __restrict__ genb,  float* __restrict__ out) {
    __shared__ float ad[S];
    __shared__ float dctx[2*H];
    __shared__ float red[256];
    int b = blockIdx.x, tid = threadIdx.x;

    float lm = -1e30f;
    for (int i = tid; i < S; i += 256) { float v = g_scores[b*S + i]; ad[i] = v; lm = fmaxf(lm, v); }
    red[tid] = lm; __syncthreads();
    for (int o = 128; o; o >>= 1) { if (tid < o) red[tid] = fmaxf(red[tid], red[tid+o]); __syncthreads(); }
    float mx = red[0];
    __syncthreads();
    float ls = 0.f;
    for (int i = tid; i < S; i += 256) { float e = __expf(ad[i] - mx); ad[i] = e; ls += e; }
    red[tid] = ls; __syncthreads();
    for (int o = 128; o; o >>= 1) { if (tid < o) red[tid] += red[tid+o]; __syncthreads(); }
    float inv = 1.f/red[0];
    __syncthreads();
    for (int i = tid; i < S; i += 256) {
        float a = ad[i]*inv; ad[i] = a;
        g_ad[b*S + i] = a;
        out[OUT_ATT + b*S + i] = a;
    }
    dctx[tid] = g_hnew[b*H + tid];
    __syncthreads();

    // context[h] = sum_s ad[s]*enc[b,s,h] — 4 accumulators for MLP
    {
        const float* ep = enc + (size_t)b*S*H + tid;
        float c0 = 0.f, c1 = 0.f, c2 = 0.f, c3 = 0.f;
        #pragma unroll 2
        for (int s = 0; s < S; s += 4) {
            c0 = fmaf(ad[s],   ep[(size_t)(s)*H],   c0);
            c1 = fmaf(ad[s+1], ep[(size_t)(s+1)*H], c1);
            c2 = fmaf(ad[s+2], ep[(size_t)(s+2)*H], c2);
            c3 = fmaf(ad[s+3], ep[(size_t)(s+3)*H], c3);
        }
        dctx[H + tid] = (c0 + c1) + (c2 + c3);
    }
    __syncthreads();

    int warp = tid >> 5, lane = tid & 31;
    for (int e0 = 0; e0 < 16; e0++) {
        int e = warp*16 + e0;
        const float* wr = outhw + (size_t)e*H2;
        float a = 0.f;
        #pragma unroll
        for (int i = 0; i < 16; i++) a = fmaf(wr[lane + i*32], dctx[lane + i*32], a);
        #pragma unroll
        for (int o = 16; o; o >>= 1) a += __shfl_xor_sync(0xffffffffu, a, o);
        if (lane == 0) g_decH[b*E + e] = a + outhb[e];
    }

    float p = 0.f;
    for (int i = tid; i < 2*H + E; i += 256) {
        float cv = (i < 2*H) ? dctx[i] : g_x[b*E + (i - 2*H)];
        p = fmaf(cv, genw[i], p);
    }
    red[tid] = p; __syncthreads();
    for (int o = 128; o; o >>= 1) { if (tid < o) red[tid] += red[tid+o]; __syncthreads(); }
    if (tid == 0) {
        float pg = 1.f/(1.f + __expf(-(red[0] + genb[0])));
        g_pgen[b] = pg;
        out[OUT_PGEN + b] = pg;
    }
}

// ---------------- D: vocab GEMM via bf16 tensor-core 2-pass split -------------
// logits = (Wh + Wl) . Dh  (Wh.Dl ~ 2^-9 rel, dropped; ~6e-4 abs on logits)
// block: 128 vocab x 128 batch.  warp tile: 32 vocab x 64 batch (8 warps).
extern __shared__ char smem_d[];
__global__ __launch_bounds__(256, 2) void k_logits(
    const float* __restrict__ Wv, const float* __restrict__ bv) {
    __nv_bfloat16* sWh = (__nv_bfloat16*)smem_d;
    __nv_bfloat16* sWl = sWh + 128*WSTR;
    __nv_bfloat16* sDh = sWl + 128*WSTR;
    float* sC    = (float*)smem_d;                    // reused after MMA passes
    float* sBias = (float*)(smem_d + 3*128*WSTR*2);

    int tid = threadIdx.x;
    int v0 = blockIdx.x*128;
    bool full = (v0 + 128 <= V);

    // load + split W tile (float4 path when fully in range)
    if (full) {
        for (int i = tid; i < 128*32; i += 256) {
            int r = i >> 5, kq = i & 31;
            float4 w4 = *(const float4*)&Wv[(size_t)(v0 + r)*E + kq*4];
            __nv_bfloat16 h0 = __float2bfloat16(w4.x);
            __nv_bfloat16 h1 = __float2bfloat16(w4.y);
            __nv_bfloat16 h2 = __float2bfloat16(w4.z);
            __nv_bfloat16 h3 = __float2bfloat16(w4.w);
            __nv_bfloat162* ph = (__nv_bfloat162*)&sWh[r*WSTR + kq*4];
            __nv_bfloat162* pl = (__nv_bfloat162*)&sWl[r*WSTR + kq*4];
            ph[0] = __nv_bfloat162(h0, h1);
            ph[1] = __nv_bfloat162(h2, h3);
            pl[0] = __nv_bfloat162(__float2bfloat16(w4.x - __bfloat162float(h0)),
                                   __float2bfloat16(w4.y - __bfloat162float(h1)));
            pl[1] = __nv_bfloat162(__float2bfloat16(w4.z - __bfloat162float(h2)),
                                   __float2bfloat16(w4.w - __bfloat162float(h3)));
        }
    } else {
        for (int i = tid; i < 128*128; i += 256) {
            int r = i >> 7, k = i & 127;
            int v = v0 + r;
            float w = (v < V) ? Wv[(size_t)v*E + k] : 0.f;
            __nv_bfloat16 hh = __float2bfloat16(w);
            sWh[r*WSTR + k] = hh;
            sWl[r*WSTR + k] = __float2bfloat16(w - __bfloat162float(hh));
        }
    }
    // dec_h -> bf16 (high part only)
    for (int i = tid; i < 128*32; i += 256) {
        int bb = i >> 5, kq = i & 31;
        float4 d4 = *(const float4*)&g_decH[bb*E + kq*4];
        __nv_bfloat162* ph = (__nv_bfloat162*)&sDh[bb*WSTR + kq*4];
        ph[0] = __nv_bfloat162(__float2bfloat16(d4.x), __float2bfloat16(d4.y));
        ph[1] = __nv_bfloat162(__float2bfloat16(d4.z), __float2bfloat16(d4.w));
    }
    if (tid < 128) sBias[tid] = (v0 + tid < V) ? bv[v0 + tid] : 0.f;
    __syncthreads();

    int warp = tid >> 5, lane = tid & 31;
    int mBase = (warp & 3)*32;     // vocab offset in tile
    int nBase = (warp >> 2)*64;    // batch offset in tile

    float acc[2][8][4];
    #pragma unroll
    for (int mi = 0; mi < 2; mi++)
        #pragma unroll
        for (int j = 0; j < 8; j++)
            #pragma unroll
            for (int q = 0; q < 4; q++) acc[mi][j][q] = 0.f;

    int aRow = mBase + (lane & 7) + ((lane >> 3) & 1)*8;
    int aK   = (lane >> 4)*8;
    int bRow = nBase + (lane & 7) + (lane >> 4)*8;
    int bK   = ((lane >> 3) & 1)*8;

    uint32_t uWh = smem_u32(sWh) + (uint32_t)(aRow*WSTR + aK)*2;
    uint32_t uWl = smem_u32(sWl) + (uint32_t)(aRow*WSTR + aK)*2;
    uint32_t uDh = smem_u32(sDh) + (uint32_t)(bRow*WSTR + bK)*2;

    #pragma unroll
    for (int k0 = 0; k0 < 128; k0 += 16) {
        uint32_t ah[2][4], al[2][4];
        #pragma unroll
        for (int mi = 0; mi < 2; mi++) {
            uint32_t adh = uWh + (uint32_t)(mi*16*WSTR + k0)*2;
            asm volatile("ldmatrix.sync.aligned.m8n8.x4.shared.b16 {%0,%1,%2,%3}, [%4];"
                : "=r"(ah[mi][0]), "=r"(ah[mi][1]), "=r"(ah[mi][2]), "=r"(ah[mi][3])
                : "r"(adh));
            uint32_t adl = uWl + (uint32_t)(mi*16*WSTR + k0)*2;
            asm volatile("ldmatrix.sync.aligned.m8n8.x4.shared.b16 {%0,%1,%2,%3}, [%4];"
                : "=r"(al[mi][0]), "=r"(al[mi][1]), "=r"(al[mi][2]), "=r"(al[mi][3])
                : "r"(adl));
        }
        #pragma unroll
        for (int jp = 0; jp < 4; jp++) {
            uint32_t bfr[4];
            uint32_t bd = uDh + (uint32_t)(jp*16*WSTR + k0)*2;
            asm volatile("ldmatrix.sync.aligned.m8n8.x4.shared.b16 {%0,%1,%2,%3}, [%4];"
                : "=r"(bfr[0]), "=r"(bfr[1]), "=r"(bfr[2]), "=r"(bfr[3])
                : "r"(bd));
            #pragma unroll
            for (int mi = 0; mi < 2; mi++) {
                asm volatile(
                    "mma.sync.aligned.m16n8k16.row.col.f32.bf16.bf16.f32 "
                    "{%0,%1,%2,%3}, {%4,%5,%6,%7}, {%8,%9}, {%0,%1,%2,%3};"
                    : "+f"(acc[mi][2*jp][0]), "+f"(acc[mi][2*jp][1]),
                      "+f"(acc[mi][2*jp][2]), "+f"(acc[mi][2*jp][3])
                    : "r"(ah[mi][0]), "r"(ah[mi][1]), "r"(ah[mi][2]), "r"(ah[mi][3]),
                      "r"(bfr[0]), "r"(bfr[1]));
                asm volatile(
                    "mma.sync.aligned.m16n8k16.row.col.f32.bf16.bf16.f32 "
                    "{%0,%1,%2,%3}, {%4,%5,%6,%7}, {%8,%9}, {%0,%1,%2,%3};"
                    : "+f"(acc[mi][2*jp][0]), "+f"(acc[mi][2*jp][1]),
                      "+f"(acc[mi][2*jp][2]), "+f"(acc[mi][2*jp][3])
                    : "r"(al[mi][0]), "r"(al[mi][1]), "r"(al[mi][2]), "r"(al[mi][3]),
                      "r"(bfr[0]), "r"(bfr[1]));
                asm volatile(
                    "mma.sync.aligned.m16n8k16.row.col.f32.bf16.bf16.f32 "
                    "{%0,%1,%2,%3}, {%4,%5,%6,%7}, {%8,%9}, {%0,%1,%2,%3};"
                    : "+f"(acc[mi][2*jp+1][0]), "+f"(acc[mi][2*jp+1][1]),
                      "+f"(acc[mi][2*jp+1][2]), "+f"(acc[mi][2*jp+1][3])
                    : "r"(ah[mi][0]), "r"(ah[mi][1]), "r"(ah[mi][2]), "r"(ah[mi][3]),
                      "r"(bfr[2]), "r"(bfr[3]));
                asm volatile(
                    "mma.sync.aligned.m16n8k16.row.col.f32.bf16.bf16.f32 "
                    "{%0,%1,%2,%3}, {%4,%5,%6,%7}, {%8,%9}, {%0,%1,%2,%3};"
                    : "+f"(acc[mi][2*jp+1][0]), "+f"(acc[mi][2*jp+1][1]),
                      "+f"(acc[mi][2*jp+1][2]), "+f"(acc[mi][2*jp+1][3])
                    : "r"(al[mi][0]), "r"(al[mi][1]), "r"(al[mi][2]), "r"(al[mi][3]),
                      "r"(bfr[2]), "r"(bfr[3]));
            }
        }
    }

    // stage C into smem (transpose to [b][v]) — reuses W region
    __syncthreads();
    #pragma unroll
    for (int mi = 0; mi < 2; mi++)
        #pragma unroll
        for (int j = 0; j < 8; j++)
            #pragma unroll
            for (int q = 0; q < 4; q++) {
                int vl = mBase + 16*mi + (lane >> 2) + ((q >> 1) ? 8 : 0);
                int bl = nBase + 8*j + 2*(lane & 3) + (q & 1);
                sC[bl*VSTR + vl] = acc[mi][j][q];
            }
    __syncthreads();

    // per-b-row: add bias, write logits, softmax partials (max, sum of exp)
    int nvalid = min(128, V - v0);
    for (int r = 0; r < 16; r++) {
        int bb = warp*16 + r;
        const float4 x4 = ((const float4*)(sC + bb*VSTR))[lane];
        int vl = lane*4;
        float val[4] = {x4.x + sBias[vl], x4.y + sBias[vl+1],
                        x4.z + sBias[vl+2], x4.w + sBias[vl+3]};
        float m = -1e30f;
        #pragma unroll
        for (int i = 0; i < 4; i++) if (vl + i < nvalid) m = fmaxf(m, val[i]);
        #pragma unroll
        for (int o = 16; o; o >>= 1) m = fmaxf(m, __shfl_xor_sync(0xffffffffu, m, o));
        float s = 0.f;
        #pragma unroll
        for (int i = 0; i < 4; i++) if (vl + i < nvalid) s += __expf(val[i] - m);
        #pragma unroll
        for (int o = 16; o; o >>= 1) s += __shfl_xor_sync(0xffffffffu, s, o);
        #pragma unroll
        for (int i = 0; i < 4; i++)
            if (vl + i < nvalid) g_logits[(size_t)bb*V + v0 + vl + i] = val[i];
        if (lane == 0) {
            g_pmax[bb*NBLK + blockIdx.x] = m;
            g_psum[bb*NBLK + blockIdx.x] = s;
        }
    }
}

// ---------------- D2: combine softmax partials (tiny) ------------------------
__global__ void k_comb() {
    __shared__ float sm[128], ss[128];
    int b = blockIdx.x, tid = threadIdx.x;
    float m = -1e30f, s = 0.f;
    for (int i = tid; i < NBLK; i += 128) {
        float pm = g_pmax[b*NBLK + i], ps = g_psum[b*NBLK + i];
        if (pm > m) { s = s*__expf(m - pm) + ps; m = pm; }
        else          s += ps*__expf(pm - m);
    }
    sm[tid] = m; ss[tid] = s; __syncthreads();
    for (int o = 64; o; o >>= 1) {
        if (tid < o) {
            float m1 = sm[tid], s1 = ss[tid];
            float m2 = sm[tid+o], s2 = ss[tid+o];
            float nm = fmaxf(m1, m2);
            sm[tid] = nm;
            ss[tid] = s1*__expf(m1 - nm) + s2*__expf(m2 - nm);
        }
        __syncthreads();
    }
    if (tid == 0) { g_rowmax[b] = sm[0]; g_rowinv[b] = 1.f/ss[0]; }
}

// ---------------- E: p_vocab + p_final (vectorized) ---------------------------
__global__ __launch_bounds__(256) void k_final(float* __restrict__ out) {
    int b = blockIdx.y;
    int v = (blockIdx.x*256 + threadIdx.x)*4;
    if (v >= VP) return;
    float pg = g_pgen[b];
    if (v < V) {
        float4 l = *(const float4*)&g_logits[(size_t)b*V + v];
        float mx = g_rowmax[b], inv = g_rowinv[b];
        float4 p;
        p.x = __expf(l.x - mx)*inv; p.y = __expf(l.y - mx)*inv;
        p.z = __expf(l.z - mx)*inv; p.w = __expf(l.w - mx)*inv;
        *(float4*)&out[OUT_PVOCAB + (size_t)b*V + v] = p;
        float2 f0 = make_float2(p.x*pg, p.y*pg);
        float2 f1 = make_float2(p.z*pg, p.w*pg);
        *(float2*)&out[OUT_PFINAL + (size_t)b*VP + v]     = f0;
        *(float2*)&out[OUT_PFINAL + (size_t)b*VP + v + 2] = f1;
    } else {
        #pragma unroll
        for (int i = 0; i < 4; i += 2)
            if (v + i < VP)
                *(float2*)&out[OUT_PFINAL + (size_t)b*VP + v + i] = make_float2(0.f, 0.f);
    }
}

// ---------------- F: pointer scatter ------------------------------------------
__global__ void k_scatter(const int* __restrict__ fiv, float* __restrict__ out) {
    int b = blockIdx.x;
    float w = 1.f - g_pgen[b];
    for (int s = threadIdx.x; s < S; s += blockDim.x) {
        int idx = fiv[b*S + s];
        atomicAdd(&out[OUT_PFINAL + (size_t)b*VP + idx], w*g_ad[b*S + s]);
    }
}

// ---------------- launcher ---------------------------------------------------
extern "C" void kernel_launch(void* const* d_in, const int* in_sizes, int n_in,
                              void* d_out, int out_size) {
    const int*   tok   = (const int*)  d_in[0];
    const float* hprev = (const float*)d_in[1];
    const float* enc   = (const float*)d_in[2];
    const int*   fiv   = (const int*)  d_in[3];
    const float* emb   = (const float*)d_in[4];
    const float* Wih   = (const float*)d_in[5];
    const float* Whh   = (const float*)d_in[6];
    const float* bih   = (const float*)d_in[7];
    const float* bhh   = (const float*)d_in[8];
    const float* wh    = (const float*)d_in[9];
    const float* ws    = (const float*)d_in[10];
    const float* ab    = (const float*)d_in[11];
    const float* av    = (const float*)d_in[12];
    const float* genw  = (const float*)d_in[13];
    const float* genb  = (const float*)d_in[14];
    const float* outhw = (const float*)d_in[15];
    const float* outhb = (const float*)d_in[16];
    const float* Wv    = (const float*)d_in[17];
    const float* bv    = (const float*)d_in[18];
    float* out = (float*)d_out;

    cudaFuncSetAttribute(k_logits, cudaFuncAttributeMaxDynamicSharedMemorySize, SMEM_D1);

    k_gates  <<<dim3(12, 8), 256>>>(tok, emb, hprev, Wih, Whh, bih, bhh);
    k_gru    <<<B, H>>>(hprev, out);
    k_scores <<<dim3(S/8, B), 256>>>(enc, wh, ws, ab, av);
    k_attn   <<<B, 256>>>(enc, outhw, outhb, genw, genb, out);
    k_logits <<<NBLK, 256, SMEM_D1>>>(Wv, bv);
    k_comb   <<<B, 128>>>();
    k_final  <<<dim3((VP + 1023)/1024, B), 256>>>(out);
    k_scatter<<<B, 256>>>(fiv, out);
}

// round 5
// speedup vs baseline: 1.3284x; 1.0405x over previous
#include <cuda_runtime.h>
#include <cuda_fp16.h>
#include <cstdint>

#define B 128
#define S 400
#define H 256
#define E 128
#define V 50000
#define PAD 250
#define VP 50250
#define H2 512
#define H3 768
#define NBLK 391            // ceil(V/128)
#define WSTR 136            // fp16 elems per smem row (bank-conflict-free ldmatrix)
#define VSTR 132            // floats per staged C row
#define CH 50               // seq rows per attention chunk
#define NCH 8               // chunks per batch row (CH*NCH == S)

// Output layout: concat of flattened (h_new, p_final, p_gen, p_vocab, att_dist)
#define OUT_HNEW   0
#define OUT_PFINAL (B*H)
#define OUT_PGEN   (OUT_PFINAL + B*VP)
#define OUT_PVOCAB (OUT_PGEN + B)
#define OUT_ATT    (OUT_PVOCAB + B*V)

#define SMEM_D1 (3*128*WSTR*2 + 128*4)          // Wh, Wl, Dh fp16 tiles + bias row
#define SMEM_P  ((CH*H + 3*H + 64)*4)           // enc chunk + wh/av/ch + scores

// ---------------- scratch (static device globals; no allocation) -------------
__device__ float g_x[B*E];
__device__ float g_hnew[B*H];
__device__ float g_gsum[B*H3];
__device__ float g_ghn[B*H];
__device__ float g_esc[B*S];         // exp(score - m_chunk)
__device__ float g_cmax[B*NCH];
__device__ float g_csum[B*NCH];
__device__ float g_pctx[B*NCH*H];    // partial contexts
__device__ float g_ad[B*S];
__device__ float g_decH[B*E];        // [b][e] fp32
__device__ float g_logits[B*V];      // 25.6 MB
__device__ float g_pmax[B*NBLK];
__device__ float g_psum[B*NBLK];
__device__ float g_rowmax[B];
__device__ float g_rowinv[B];
__device__ float g_pgen[B];

__device__ __forceinline__ float tanh_hw(float x) {
    float y;
    asm("tanh.approx.f32 %0, %1;" : "=f"(y) : "f"(x));
    return y;
}

__device__ __forceinline__ uint32_t smem_u32(const void* p) {
    return (uint32_t)__cvta_generic_to_shared(p);
}

// ---------------- A1: GRU gate GEMMs (embedding gather fused in) -------------
__global__ __launch_bounds__(256) void k_gates(
    const int* __restrict__ tok,    const float* __restrict__ emb,
    const float* __restrict__ hprev, const float* __restrict__ Wih,
    const float* __restrict__ Whh,  const float* __restrict__ bih,
    const float* __restrict__ bhh) {
    __shared__ float xhT[384*20];
    __shared__ float wT[64*65];
    __shared__ int   s_tok[16];
    int j0 = blockIdx.x*64, b0 = blockIdx.y*16;
    int tid = threadIdx.x;

    if (tid < 16) s_tok[tid] = tok[b0 + tid];
    __syncthreads();

    for (int i = tid; i < 16*384; i += 256) {
        int bl = i/384, k = i%384;
        float v = (k < 128) ? emb[(size_t)s_tok[bl]*E + k] : hprev[(b0+bl)*H + (k-128)];
        xhT[k*20 + bl] = v;
        if (blockIdx.x == 0 && k < 128) g_x[(b0+bl)*E + k] = v;
    }

    int j_loc = tid & 63, bq = tid >> 6;
    int j = j0 + j_loc;
    bool isN = (j >= 2*H);
    float acc[4]  = {0.f,0.f,0.f,0.f};
    float accn[4] = {0.f,0.f,0.f,0.f};

    for (int kt = 0; kt < 384; kt += 64) {
        __syncthreads();
        for (int i = tid; i < 64*64; i += 256) {
            int jl = i >> 6, kk = i & 63;
            int k = kt + kk, jj = j0 + jl;
            float w = (k < 128) ? Wih[(size_t)jj*E + k] : Whh[(size_t)jj*H + (k-128)];
            wT[kk*65 + jl] = w;
        }
        __syncthreads();
        if (kt < 128) {
            #pragma unroll 8
            for (int kk = 0; kk < 64; kk++) {
                float w = wT[kk*65 + j_loc];
                float4 xv = *(const float4*)&xhT[(kt+kk)*20 + bq*4];
                acc[0] = fmaf(w, xv.x, acc[0]); acc[1] = fmaf(w, xv.y, acc[1]);
                acc[2] = fmaf(w, xv.z, acc[2]); acc[3] = fmaf(w, xv.w, acc[3]);
            }
        } else {
            #pragma unroll 8
            for (int kk = 0; kk < 64; kk++) {
                float w = wT[kk*65 + j_loc];
                float4 xv = *(const float4*)&xhT[(kt+kk)*20 + bq*4];
                acc[0] = fmaf(w, xv.x, acc[0]); acc[1] = fmaf(w, xv.y, acc[1]);
                acc[2] = fmaf(w, xv.z, acc[2]); acc[3] = fmaf(w, xv.w, acc[3]);
                accn[0] = fmaf(w, xv.x, accn[0]); accn[1] = fmaf(w, xv.y, accn[1]);
                accn[2] = fmaf(w, xv.z, accn[2]); accn[3] = fmaf(w, xv.w, accn[3]);
            }
        }
    }
    float bs = bih[j] + bhh[j];
    #pragma unroll
    for (int i = 0; i < 4; i++) {
        int b = b0 + bq*4 + i;
        g_gsum[b*H3 + j] = acc[i] + bs;
        if (isN) g_ghn[b*H + (j - 2*H)] = accn[i] + bhh[j];
    }
}

// ---------------- A2: GRU elementwise (precise: h_new dominates out norm) ----
__global__ void k_gru(const float* __restrict__ hprev, float* __restrict__ out) {
    int b = blockIdx.x, j = threadIdx.x;
    float gr = g_gsum[b*H3 + j];
    float gz = g_gsum[b*H3 + H + j];
    float gn = g_gsum[b*H3 + 2*H + j];
    float hn = g_ghn[b*H + j];
    float r = 1.f/(1.f + __expf(-gr));
    float z = 1.f/(1.f + __expf(-gz));
    float n = tanhf(gn + (r - 1.f)*hn);
    float h = (1.f - z)*n + z*hprev[b*H + j];
    g_hnew[b*H + j] = h;
    out[OUT_HNEW + b*H + j] = h;
}

// ---------------- B: fused scores + chunk softmax + partial context ----------
// grid (NCH, B). One enc chunk (50x256) staged in smem, read from DRAM once.
extern __shared__ float smem_p[];
__global__ __launch_bounds__(256) void k_part(
    const float* __restrict__ enc, const float* __restrict__ wh,
    const float* __restrict__ ws,  const float* __restrict__ ab,
    const float* __restrict__ av) {
    float* sEnc = smem_p;               // [CH][H]
    float* s_wh = sEnc + CH*H;
    float* s_av = s_wh + H;
    float* s_ch = s_av + H;
    float* sSc  = s_ch + H;             // [CH] scores then exp values

    int c = blockIdx.x, b = blockIdx.y;
    int tid = threadIdx.x;
    int warp = tid >> 5, lane = tid & 31;

    s_wh[tid] = wh[tid];
    s_av[tid] = av[tid];
    s_ch[tid] = fmaf(ws[tid], g_hnew[b*H + tid], ab[0]);

    // stage enc chunk (coalesced float4)
    {
        const float4* src = (const float4*)(enc + ((size_t)b*S + c*CH)*H);
        float4* dst = (float4*)sEnc;
        #pragma unroll
        for (int i = tid; i < CH*H/4; i += 256) dst[i] = src[i];
    }
    __syncthreads();

    // scores: warp per row
    for (int s = warp; s < CH; s += 8) {
        const float* ep = sEnc + s*H;
        int h0 = lane*4;
        float acc = 0.f;
        float4 e0 = *(const float4*)&ep[h0];
        float4 w0 = *(const float4*)&s_wh[h0];
        float4 c0 = *(const float4*)&s_ch[h0];
        float4 a0 = *(const float4*)&s_av[h0];
        acc = fmaf(tanh_hw(fmaf(w0.x, e0.x, c0.x)), a0.x, acc);
        acc = fmaf(tanh_hw(fmaf(w0.y, e0.y, c0.y)), a0.y, acc);
        acc = fmaf(tanh_hw(fmaf(w0.z, e0.z, c0.z)), a0.z, acc);
        acc = fmaf(tanh_hw(fmaf(w0.w, e0.w, c0.w)), a0.w, acc);
        float4 e1 = *(const float4*)&ep[h0 + 128];
        float4 w1 = *(const float4*)&s_wh[h0 + 128];
        float4 c1 = *(const float4*)&s_ch[h0 + 128];
        float4 a1 = *(const float4*)&s_av[h0 + 128];
        acc = fmaf(tanh_hw(fmaf(w1.x, e1.x, c1.x)), a1.x, acc);
        acc = fmaf(tanh_hw(fmaf(w1.y, e1.y, c1.y)), a1.y, acc);
        acc = fmaf(tanh_hw(fmaf(w1.z, e1.z, c1.z)), a1.z, acc);
        acc = fmaf(tanh_hw(fmaf(w1.w, e1.w, c1.w)), a1.w, acc);
        #pragma unroll
        for (int o = 16; o; o >>= 1) acc += __shfl_xor_sync(0xffffffffu, acc, o);
        if (lane == 0) sSc[s] = acc;
    }
    __syncthreads();

    // chunk-local max / exp / sum (warp 0)
    if (warp == 0) {
        float v0 = (lane      < CH) ? sSc[lane]      : -1e30f;
        float v1 = (lane + 32 < CH) ? sSc[lane + 32] : -1e30f;
        float m = fmaxf(v0, v1);
        #pragma unroll
        for (int o = 16; o; o >>= 1) m = fmaxf(m, __shfl_xor_sync(0xffffffffu, m, o));
        float e0 = (lane      < CH) ? __expf(v0 - m) : 0.f;
        float e1 = (lane + 32 < CH) ? __expf(v1 - m) : 0.f;
        if (lane      < CH) { sSc[lane]      = e0; g_esc[b*S + c*CH + lane]      = e0; }
        if (lane + 32 < CH) { sSc[lane + 32] = e1; g_esc[b*S + c*CH + lane + 32] = e1; }
        float s = e0 + e1;
        #pragma unroll
        for (int o = 16; o; o >>= 1) s += __shfl_xor_sync(0xffffffffu, s, o);
        if (lane == 0) { g_cmax[b*NCH + c] = m; g_csum[b*NCH + c] = s; }
    }
    __syncthreads();

    // partial context: thread per h-column, conflict-free smem
    {
        float c0 = 0.f, c1 = 0.f, c2 = 0.f, c3 = 0.f;
        #pragma unroll 4
        for (int s = 0; s < 48; s += 4) {
            c0 = fmaf(sSc[s],   sEnc[(s)*H + tid],   c0);
            c1 = fmaf(sSc[s+1], sEnc[(s+1)*H + tid], c1);
            c2 = fmaf(sSc[s+2], sEnc[(s+2)*H + tid], c2);
            c3 = fmaf(sSc[s+3], sEnc[(s+3)*H + tid], c3);
        }
        c0 = fmaf(sSc[48], sEnc[48*H + tid], c0);
        c1 = fmaf(sSc[49], sEnc[49*H + tid], c1);
        g_pctx[(b*NCH + c)*H + tid] = (c0 + c1) + (c2 + c3);
    }
}

// ---------------- C: combine partials + att_dist + dec_h + p_gen -------------
__global__ __launch_bounds__(256) void k_comb_att(
    const float* __restrict__ outhw, const float* __restrict__ outhb,
    const float* __restrict__ genw,  const float* __restrict__ genb,
    float* __restrict__ out) {
    __shared__ float dctx[2*H];
    __shared__ float red[256];
    __shared__ float sW[NCH];
    int b = blockIdx.x, tid = threadIdx.x;

    if (tid == 0) {
        float m[NCH], sm = -1e30f;
        #pragma unroll
        for (int c = 0; c < NCH; c++) { m[c] = g_cmax[b*NCH + c]; sm = fmaxf(sm, m[c]); }
        float L = 0.f;
        #pragma unroll
        for (int c = 0; c < NCH; c++) L += g_csum[b*NCH + c]*__expf(m[c] - sm);
        float invL = 1.f/L;
        #pragma unroll
        for (int c = 0; c < NCH; c++) sW[c] = __expf(m[c] - sm)*invL;
    }
    __syncthreads();

    // att_dist
    for (int i = tid; i < S; i += 256) {
        float a = g_esc[b*S + i]*sW[i/CH];
        g_ad[b*S + i] = a;
        out[OUT_ATT + b*S + i] = a;
    }

    // context
    {
        float ctx = 0.f;
        #pragma unroll
        for (int c = 0; c < NCH; c++) ctx = fmaf(g_pctx[(b*NCH + c)*H + tid], sW[c], ctx);
        dctx[H + tid] = ctx;
    }
    dctx[tid] = g_hnew[b*H + tid];
    __syncthreads();

    int warp = tid >> 5, lane = tid & 31;
    for (int e0 = 0; e0 < 16; e0++) {
        int e = warp*16 + e0;
        const float* wr = outhw + (size_t)e*H2;
        float a = 0.f;
        #pragma unroll
        for (int i = 0; i < 16; i++) a = fmaf(wr[lane + i*32], dctx[lane + i*32], a);
        #pragma unroll
        for (int o = 16; o; o >>= 1) a += __shfl_xor_sync(0xffffffffu, a, o);
        if (lane == 0) g_decH[b*E + e] = a + outhb[e];
    }

    float p = 0.f;
    for (int i = tid; i < 2*H + E; i += 256) {
        float cv = (i < 2*H) ? dctx[i] : g_x[b*E + (i - 2*H)];
        p = fmaf(cv, genw[i], p);
    }
    red[tid] = p; __syncthreads();
    for (int o = 128; o; o >>= 1) { if (tid < o) red[tid] += red[tid+o]; __syncthreads(); }
    if (tid == 0) {
        float pg = 1.f/(1.f + __expf(-(red[0] + genb[0])));
        g_pgen[b] = pg;
        out[OUT_PGEN + b] = pg;
    }
}

// ---------------- D: vocab GEMM via fp16 tensor-core 2-pass split -------------
// logits = (Wh + Wl) . Dh  with fp16 split (Dl residual ~2^-11, dropped)
extern __shared__ char smem_d[];
__global__ __launch_bounds__(256, 2) void k_logits(
    const float* __restrict__ Wv, const float* __restrict__ bv) {
    __half* sWh = (__half*)smem_d;
    __half* sWl = sWh + 128*WSTR;
    __half* sDh = sWl + 128*WSTR;
    float* sC    = (float*)smem_d;                    // reused after MMA passes
    float* sBias = (float*)(smem_d + 3*128*WSTR*2);

    int tid = threadIdx.x;
    int v0 = blockIdx.x*128;
    bool full = (v0 + 128 <= V);

    if (full) {
        for (int i = tid; i < 128*32; i += 256) {
            int r = i >> 5, kq = i & 31;
            float4 w4 = *(const float4*)&Wv[(size_t)(v0 + r)*E + kq*4];
            __half h0 = __float2half(w4.x), h1 = __float2half(w4.y);
            __half h2 = __float2half(w4.z), h3 = __float2half(w4.w);
            __half2* ph = (__half2*)&sWh[r*WSTR + kq*4];
            __half2* pl = (__half2*)&sWl[r*WSTR + kq*4];
            ph[0] = __half2(h0, h1);
            ph[1] = __half2(h2, h3);
            pl[0] = __half2(__float2half(w4.x - __half2float(h0)),
                            __float2half(w4.y - __half2float(h1)));
            pl[1] = __half2(__float2half(w4.z - __half2float(h2)),
                            __float2half(w4.w - __half2float(h3)));
        }
    } else {
        for (int i = tid; i < 128*128; i += 256) {
            int r = i >> 7, k = i & 127;
            int v = v0 + r;
            float w = (v < V) ? Wv[(size_t)v*E + k] : 0.f;
            __half hh = __float2half(w);
            sWh[r*WSTR + k] = hh;
            sWl[r*WSTR + k] = __float2half(w - __half2float(hh));
        }
    }
    for (int i = tid; i < 128*32; i += 256) {
        int bb = i >> 5, kq = i & 31;
        float4 d4 = *(const float4*)&g_decH[bb*E + kq*4];
        __half2* ph = (__half2*)&sDh[bb*WSTR + kq*4];
        ph[0] = __half2(__float2half(d4.x), __float2half(d4.y));
        ph[1] = __half2(__float2half(d4.z), __float2half(d4.w));
    }
    if (tid < 128) sBias[tid] = (v0 + tid < V) ? bv[v0 + tid] : 0.f;
    __syncthreads();

    int warp = tid >> 5, lane = tid & 31;
    int mBase = (warp & 3)*32;     // vocab offset in tile
    int nBase = (warp >> 2)*64;    // batch offset in tile

    float acc[2][8][4];
    #pragma unroll
    for (int mi = 0; mi < 2; mi++)
        #pragma unroll
        for (int j = 0; j < 8; j++)
            #pragma unroll
            for (int q = 0; q < 4; q++) acc[mi][j][q] = 0.f;

    int aRow = mBase + (lane & 7) + ((lane >> 3) & 1)*8;
    int aK   = (lane >> 4)*8;
    int bRow = nBase + (lane & 7) + (lane >> 4)*8;
    int bK   = ((lane >> 3) & 1)*8;

    uint32_t uWh = smem_u32(sWh) + (uint32_t)(aRow*WSTR + aK)*2;
    uint32_t uWl = smem_u32(sWl) + (uint32_t)(aRow*WSTR + aK)*2;
    uint32_t uDh = smem_u32(sDh) + (uint32_t)(bRow*WSTR + bK)*2;

    #pragma unroll
    for (int k0 = 0; k0 < 128; k0 += 16) {
        uint32_t ah[2][4], al[2][4];
        #pragma unroll
        for (int mi = 0; mi < 2; mi++) {
            uint32_t adh = uWh + (uint32_t)(mi*16*WSTR + k0)*2;
            asm volatile("ldmatrix.sync.aligned.m8n8.x4.shared.b16 {%0,%1,%2,%3}, [%4];"
                : "=r"(ah[mi][0]), "=r"(ah[mi][1]), "=r"(ah[mi][2]), "=r"(ah[mi][3])
                : "r"(adh));
            uint32_t adl = uWl + (uint32_t)(mi*16*WSTR + k0)*2;
            asm volatile("ldmatrix.sync.aligned.m8n8.x4.shared.b16 {%0,%1,%2,%3}, [%4];"
                : "=r"(al[mi][0]), "=r"(al[mi][1]), "=r"(al[mi][2]), "=r"(al[mi][3])
                : "r"(adl));
        }
        #pragma unroll
        for (int jp = 0; jp < 4; jp++) {
            uint32_t bfr[4];
            uint32_t bd = uDh + (uint32_t)(jp*16*WSTR + k0)*2;
            asm volatile("ldmatrix.sync.aligned.m8n8.x4.shared.b16 {%0,%1,%2,%3}, [%4];"
                : "=r"(bfr[0]), "=r"(bfr[1]), "=r"(bfr[2]), "=r"(bfr[3])
                : "r"(bd));
            #pragma unroll
            for (int mi = 0; mi < 2; mi++) {
                asm volatile(
                    "mma.sync.aligned.m16n8k16.row.col.f32.f16.f16.f32 "
                    "{%0,%1,%2,%3}, {%4,%5,%6,%7}, {%8,%9}, {%0,%1,%2,%3};"
                    : "+f"(acc[mi][2*jp][0]), "+f"(acc[mi][2*jp][1]),
                      "+f"(acc[mi][2*jp][2]), "+f"(acc[mi][2*jp][3])
                    : "r"(ah[mi][0]), "r"(ah[mi][1]), "r"(ah[mi][2]), "r"(ah[mi][3]),
                      "r"(bfr[0]), "r"(bfr[1]));
                asm volatile(
                    "mma.sync.aligned.m16n8k16.row.col.f32.f16.f16.f32 "
                    "{%0,%1,%2,%3}, {%4,%5,%6,%7}, {%8,%9}, {%0,%1,%2,%3};"
                    : "+f"(acc[mi][2*jp][0]), "+f"(acc[mi][2*jp][1]),
                      "+f"(acc[mi][2*jp][2]), "+f"(acc[mi][2*jp][3])
                    : "r"(al[mi][0]), "r"(al[mi][1]), "r"(al[mi][2]), "r"(al[mi][3]),
                      "r"(bfr[0]), "r"(bfr[1]));
                asm volatile(
                    "mma.sync.aligned.m16n8k16.row.col.f32.f16.f16.f32 "
                    "{%0,%1,%2,%3}, {%4,%5,%6,%7}, {%8,%9}, {%0,%1,%2,%3};"
                    : "+f"(acc[mi][2*jp+1][0]), "+f"(acc[mi][2*jp+1][1]),
                      "+f"(acc[mi][2*jp+1][2]), "+f"(acc[mi][2*jp+1][3])
                    : "r"(ah[mi][0]), "r"(ah[mi][1]), "r"(ah[mi][2]), "r"(ah[mi][3]),
                      "r"(bfr[2]), "r"(bfr[3]));
                asm volatile(
                    "mma.sync.aligned.m16n8k16.row.col.f32.f16.f16.f32 "
                    "{%0,%1,%2,%3}, {%4,%5,%6,%7}, {%8,%9}, {%0,%1,%2,%3};"
                    : "+f"(acc[mi][2*jp+1][0]), "+f"(acc[mi][2*jp+1][1]),
                      "+f"(acc[mi][2*jp+1][2]), "+f"(acc[mi][2*jp+1][3])
                    : "r"(al[mi][0]), "r"(al[mi][1]), "r"(al[mi][2]), "r"(al[mi][3]),
                      "r"(bfr[2]), "r"(bfr[3]));
            }
        }
    }

    __syncthreads();
    #pragma unroll
    for (int mi = 0; mi < 2; mi++)
        #pragma unroll
        for (int j = 0; j < 8; j++)
            #pragma unroll
            for (int q = 0; q < 4; q++) {
                int vl = mBase + 16*mi + (lane >> 2) + ((q >> 1) ? 8 : 0);
                int bl = nBase + 8*j + 2*(lane & 3) + (q & 1);
                sC[bl*VSTR + vl] = acc[mi][j][q];
            }
    __syncthreads();

    int nvalid = min(128, V - v0);
    for (int r = 0; r < 16; r++) {
        int bb = warp*16 + r;
        const float4 x4 = ((const float4*)(sC + bb*VSTR))[lane];
        int vl = lane*4;
        float val[4] = {x4.x + sBias[vl], x4.y + sBias[vl+1],
                        x4.z + sBias[vl+2], x4.w + sBias[vl+3]};
        float m = -1e30f;
        #pragma unroll
        for (int i = 0; i < 4; i++) if (vl + i < nvalid) m = fmaxf(m, val[i]);
        #pragma unroll
        for (int o = 16; o; o >>= 1) m = fmaxf(m, __shfl_xor_sync(0xffffffffu, m, o));
        float s = 0.f;
        #pragma unroll
        for (int i = 0; i < 4; i++) if (vl + i < nvalid) s += __expf(val[i] - m);
        #pragma unroll
        for (int o = 16; o; o >>= 1) s += __shfl_xor_sync(0xffffffffu, s, o);
        #pragma unroll
        for (int i = 0; i < 4; i++)
            if (vl + i < nvalid) g_logits[(size_t)bb*V + v0 + vl + i] = val[i];
        if (lane == 0) {
            g_pmax[bb*NBLK + blockIdx.x] = m;
            g_psum[bb*NBLK + blockIdx.x] = s;
        }
    }
}

// ---------------- D2: combine softmax partials (tiny) ------------------------
__global__ void k_comb() {
    __shared__ float sm[128], ss[128];
    int b = blockIdx.x, tid = threadIdx.x;
    float m = -1e30f, s = 0.f;
    for (int i = tid; i < NBLK; i += 128) {
        float pm = g_pmax[b*NBLK + i], ps = g_psum[b*NBLK + i];
        if (pm > m) { s = s*__expf(m - pm) + ps; m = pm; }
        else          s += ps*__expf(pm - m);
    }
    sm[tid] = m; ss[tid] = s; __syncthreads();
    for (int o = 64; o; o >>= 1) {
        if (tid < o) {
            float m1 = sm[tid], s1 = ss[tid];
            float m2 = sm[tid+o], s2 = ss[tid+o];
            float nm = fmaxf(m1, m2);
            sm[tid] = nm;
            ss[tid] = s1*__expf(m1 - nm) + s2*__expf(m2 - nm);
        }
        __syncthreads();
    }
    if (tid == 0) { g_rowmax[b] = sm[0]; g_rowinv[b] = 1.f/ss[0]; }
}

// ---------------- E: p_vocab + p_final (vectorized) ---------------------------
__global__ __launch_bounds__(256) void k_final(float* __restrict__ out) {
    int b = blockIdx.y;
    int v = (blockIdx.x*256 + threadIdx.x)*4;
    if (v >= VP) return;
    float pg = g_pgen[b];
    if (v < V) {
        float4 l = *(const float4*)&g_logits[(size_t)b*V + v];
        float mx = g_rowmax[b], inv = g_rowinv[b];
        float4 p;
        p.x = __expf(l.x - mx)*inv; p.y = __expf(l.y - mx)*inv;
        p.z = __expf(l.z - mx)*inv; p.w = __expf(l.w - mx)*inv;
        *(float4*)&out[OUT_PVOCAB + (size_t)b*V + v] = p;
        float2 f0 = make_float2(p.x*pg, p.y*pg);
        float2 f1 = make_float2(p.z*pg, p.w*pg);
        *(float2*)&out[OUT_PFINAL + (size_t)b*VP + v]     = f0;
        *(float2*)&out[OUT_PFINAL + (size_t)b*VP + v + 2] = f1;
    } else {
        #pragma unroll
        for (int i = 0; i < 4; i += 2)
            if (v + i < VP)
                *(float2*)&out[OUT_PFINAL + (size_t)b*VP + v + i] = make_float2(0.f, 0.f);
    }
}

// ---------------- F: pointer scatter ------------------------------------------
__global__ void k_scatter(const int* __restrict__ fiv, float* __restrict__ out) {
    int b = blockIdx.x;
    float w = 1.f - g_pgen[b];
    for (int s = threadIdx.x; s < S; s += blockDim.x) {
        int idx = fiv[b*S + s];
        atomicAdd(&out[OUT_PFINAL + (size_t)b*VP + idx], w*g_ad[b*S + s]);
    }
}

// ---------------- launcher ---------------------------------------------------
extern "C" void kernel_launch(void* const* d_in, const int* in_sizes, int n_in,
                              void* d_out, int out_size) {
    const int*   tok   = (const int*)  d_in[0];
    const float* hprev = (const float*)d_in[1];
    const float* enc   = (const float*)d_in[2];
    const int*   fiv   = (const int*)  d_in[3];
    const float* emb   = (const float*)d_in[4];
    const float* Wih   = (const float*)d_in[5];
    const float* Whh   = (const float*)d_in[6];
    const float* bih   = (const float*)d_in[7];
    const float* bhh   = (const float*)d_in[8];
    const float* wh    = (const float*)d_in[9];
    const float* ws    = (const float*)d_in[10];
    const float* ab    = (const float*)d_in[11];
    const float* av    = (const float*)d_in[12];
    const float* genw  = (const float*)d_in[13];
    const float* genb  = (const float*)d_in[14];
    const float* outhw = (const float*)d_in[15];
    const float* outhb = (const float*)d_in[16];
    const float* Wv    = (const float*)d_in[17];
    const float* bv    = (const float*)d_in[18];
    float* out = (float*)d_out;

    cudaFuncSetAttribute(k_logits, cudaFuncAttributeMaxDynamicSharedMemorySize, SMEM_D1);
    cudaFuncSetAttribute(k_part,   cudaFuncAttributeMaxDynamicSharedMemorySize, SMEM_P);

    k_gates   <<<dim3(12, 8), 256>>>(tok, emb, hprev, Wih, Whh, bih, bhh);
    k_gru     <<<B, H>>>(hprev, out);
    k_part    <<<dim3(NCH, B), 256, SMEM_P>>>(enc, wh, ws, ab, av);
    k_comb_att<<<B, 256>>>(outhw, outhb, genw, genb, out);
    k_logits  <<<NBLK, 256, SMEM_D1>>>(Wv, bv);
    k_comb    <<<B, 128>>>();
    k_final   <<<dim3((VP + 1023)/1024, B), 256>>>(out);
    k_scatter <<<B, 256>>>(fiv, out);
}

// round 6
// speedup vs baseline: 1.4708x; 1.1072x over previous
#include <cuda_runtime.h>
#include <cuda_fp16.h>
#include <cstdint>

#define B 128
#define S 400
#define H 256
#define E 128
#define V 50000
#define PAD 250
#define VP 50250
#define H2 512
#define H3 768
#define NBLK 391            // ceil(V/128)
#define WSTR 136            // fp16 elems per smem row (bank-conflict-free ldmatrix)
#define VSTR 132            // floats per staged C row
#define CH 50               // seq rows per attention chunk
#define NCH 8               // chunks per batch row (CH*NCH == S)

// Output layout: concat of flattened (h_new, p_final, p_gen, p_vocab, att_dist)
#define OUT_HNEW   0
#define OUT_PFINAL (B*H)
#define OUT_PGEN   (OUT_PFINAL + B*VP)
#define OUT_PVOCAB (OUT_PGEN + B)
#define OUT_ATT    (OUT_PVOCAB + B*V)

#define SMEM_D1 (2*128*WSTR*2 + 128*4)          // Wh, Dh fp16 tiles + bias row
#define SMEM_P  ((CH*H + 3*H + 64)*4)           // enc chunk + wh/av/ch + scores

// ---------------- scratch (static device globals; no allocation) -------------
__device__ float g_x[B*E];
__device__ float g_hnew[B*H];
__device__ float g_gsum[B*H3];
__device__ float g_ghn[B*H];
__device__ float g_esc[B*S];         // exp(score - m_chunk)
__device__ float g_cmax[B*NCH];
__device__ float g_csum[B*NCH];
__device__ float g_pctx[B*NCH*H];    // partial contexts
__device__ float g_ad[B*S];
__device__ float g_decH[B*E];        // [b][e] fp32
__device__ float g_logits[B*V];      // 25.6 MB
__device__ float g_pmax[B*NBLK];
__device__ float g_psum[B*NBLK];
__device__ float g_rowmax[B];
__device__ float g_rowinv[B];
__device__ float g_pgen[B];

__device__ __forceinline__ float tanh_hw(float x) {
    float y;
    asm("tanh.approx.f32 %0, %1;" : "=f"(y) : "f"(x));
    return y;
}

__device__ __forceinline__ uint32_t smem_u32(const void* p) {
    return (uint32_t)__cvta_generic_to_shared(p);
}

// ---------------- A1: GRU gate GEMMs (embedding gather fused in) -------------
__global__ __launch_bounds__(256) void k_gates(
    const int* __restrict__ tok,    const float* __restrict__ emb,
    const float* __restrict__ hprev, const float* __restrict__ Wih,
    const float* __restrict__ Whh,  const float* __restrict__ bih,
    const float* __restrict__ bhh) {
    __shared__ float xhT[384*20];
    __shared__ float wT[64*65];
    __shared__ int   s_tok[16];
    int j0 = blockIdx.x*64, b0 = blockIdx.y*16;
    int tid = threadIdx.x;

    if (tid < 16) s_tok[tid] = tok[b0 + tid];
    __syncthreads();

    for (int i = tid; i < 16*384; i += 256) {
        int bl = i/384, k = i%384;
        float v = (k < 128) ? emb[(size_t)s_tok[bl]*E + k] : hprev[(b0+bl)*H + (k-128)];
        xhT[k*20 + bl] = v;
        if (blockIdx.x == 0 && k < 128) g_x[(b0+bl)*E + k] = v;
    }

    int j_loc = tid & 63, bq = tid >> 6;
    int j = j0 + j_loc;
    bool isN = (j >= 2*H);
    float acc[4]  = {0.f,0.f,0.f,0.f};
    float accn[4] = {0.f,0.f,0.f,0.f};

    for (int kt = 0; kt < 384; kt += 64) {
        __syncthreads();
        for (int i = tid; i < 64*64; i += 256) {
            int jl = i >> 6, kk = i & 63;
            int k = kt + kk, jj = j0 + jl;
            float w = (k < 128) ? Wih[(size_t)jj*E + k] : Whh[(size_t)jj*H + (k-128)];
            wT[kk*65 + jl] = w;
        }
        __syncthreads();
        if (kt < 128) {
            #pragma unroll 8
            for (int kk = 0; kk < 64; kk++) {
                float w = wT[kk*65 + j_loc];
                float4 xv = *(const float4*)&xhT[(kt+kk)*20 + bq*4];
                acc[0] = fmaf(w, xv.x, acc[0]); acc[1] = fmaf(w, xv.y, acc[1]);
                acc[2] = fmaf(w, xv.z, acc[2]); acc[3] = fmaf(w, xv.w, acc[3]);
            }
        } else {
            #pragma unroll 8
            for (int kk = 0; kk < 64; kk++) {
                float w = wT[kk*65 + j_loc];
                float4 xv = *(const float4*)&xhT[(kt+kk)*20 + bq*4];
                acc[0] = fmaf(w, xv.x, acc[0]); acc[1] = fmaf(w, xv.y, acc[1]);
                acc[2] = fmaf(w, xv.z, acc[2]); acc[3] = fmaf(w, xv.w, acc[3]);
                accn[0] = fmaf(w, xv.x, accn[0]); accn[1] = fmaf(w, xv.y, accn[1]);
                accn[2] = fmaf(w, xv.z, accn[2]); accn[3] = fmaf(w, xv.w, accn[3]);
            }
        }
    }
    float bs = bih[j] + bhh[j];
    #pragma unroll
    for (int i = 0; i < 4; i++) {
        int b = b0 + bq*4 + i;
        g_gsum[b*H3 + j] = acc[i] + bs;
        if (isN) g_ghn[b*H + (j - 2*H)] = accn[i] + bhh[j];
    }
}

// ---------------- A2: GRU elementwise (precise: h_new dominates out norm) ----
__global__ void k_gru(const float* __restrict__ hprev, float* __restrict__ out) {
    int b = blockIdx.x, j = threadIdx.x;
    float gr = g_gsum[b*H3 + j];
    float gz = g_gsum[b*H3 + H + j];
    float gn = g_gsum[b*H3 + 2*H + j];
    float hn = g_ghn[b*H + j];
    float r = 1.f/(1.f + __expf(-gr));
    float z = 1.f/(1.f + __expf(-gz));
    float n = tanhf(gn + (r - 1.f)*hn);
    float h = (1.f - z)*n + z*hprev[b*H + j];
    g_hnew[b*H + j] = h;
    out[OUT_HNEW + b*H + j] = h;
}

// ---------------- B: fused scores + chunk softmax + partial context ----------
extern __shared__ float smem_p[];
__global__ __launch_bounds__(256) void k_part(
    const float* __restrict__ enc, const float* __restrict__ wh,
    const float* __restrict__ ws,  const float* __restrict__ ab,
    const float* __restrict__ av) {
    float* sEnc = smem_p;               // [CH][H]
    float* s_wh = sEnc + CH*H;
    float* s_av = s_wh + H;
    float* s_ch = s_av + H;
    float* sSc  = s_ch + H;             // [CH] scores then exp values

    int c = blockIdx.x, b = blockIdx.y;
    int tid = threadIdx.x;
    int warp = tid >> 5, lane = tid & 31;

    s_wh[tid] = wh[tid];
    s_av[tid] = av[tid];
    s_ch[tid] = fmaf(ws[tid], g_hnew[b*H + tid], ab[0]);

    {
        const float4* src = (const float4*)(enc + ((size_t)b*S + c*CH)*H);
        float4* dst = (float4*)sEnc;
        #pragma unroll
        for (int i = tid; i < CH*H/4; i += 256) dst[i] = src[i];
    }
    __syncthreads();

    for (int s = warp; s < CH; s += 8) {
        const float* ep = sEnc + s*H;
        int h0 = lane*4;
        float acc = 0.f;
        float4 e0 = *(const float4*)&ep[h0];
        float4 w0 = *(const float4*)&s_wh[h0];
        float4 c0 = *(const float4*)&s_ch[h0];
        float4 a0 = *(const float4*)&s_av[h0];
        acc = fmaf(tanh_hw(fmaf(w0.x, e0.x, c0.x)), a0.x, acc);
        acc = fmaf(tanh_hw(fmaf(w0.y, e0.y, c0.y)), a0.y, acc);
        acc = fmaf(tanh_hw(fmaf(w0.z, e0.z, c0.z)), a0.z, acc);
        acc = fmaf(tanh_hw(fmaf(w0.w, e0.w, c0.w)), a0.w, acc);
        float4 e1 = *(const float4*)&ep[h0 + 128];
        float4 w1 = *(const float4*)&s_wh[h0 + 128];
        float4 c1 = *(const float4*)&s_ch[h0 + 128];
        float4 a1 = *(const float4*)&s_av[h0 + 128];
        acc = fmaf(tanh_hw(fmaf(w1.x, e1.x, c1.x)), a1.x, acc);
        acc = fmaf(tanh_hw(fmaf(w1.y, e1.y, c1.y)), a1.y, acc);
        acc = fmaf(tanh_hw(fmaf(w1.z, e1.z, c1.z)), a1.z, acc);
        acc = fmaf(tanh_hw(fmaf(w1.w, e1.w, c1.w)), a1.w, acc);
        #pragma unroll
        for (int o = 16; o; o >>= 1) acc += __shfl_xor_sync(0xffffffffu, acc, o);
        if (lane == 0) sSc[s] = acc;
    }
    __syncthreads();

    if (warp == 0) {
        float v0 = (lane      < CH) ? sSc[lane]      : -1e30f;
        float v1 = (lane + 32 < CH) ? sSc[lane + 32] : -1e30f;
        float m = fmaxf(v0, v1);
        #pragma unroll
        for (int o = 16; o; o >>= 1) m = fmaxf(m, __shfl_xor_sync(0xffffffffu, m, o));
        float e0 = (lane      < CH) ? __expf(v0 - m) : 0.f;
        float e1 = (lane + 32 < CH) ? __expf(v1 - m) : 0.f;
        if (lane      < CH) { sSc[lane]      = e0; g_esc[b*S + c*CH + lane]      = e0; }
        if (lane + 32 < CH) { sSc[lane + 32] = e1; g_esc[b*S + c*CH + lane + 32] = e1; }
        float s = e0 + e1;
        #pragma unroll
        for (int o = 16; o; o >>= 1) s += __shfl_xor_sync(0xffffffffu, s, o);
        if (lane == 0) { g_cmax[b*NCH + c] = m; g_csum[b*NCH + c] = s; }
    }
    __syncthreads();

    {
        float c0 = 0.f, c1 = 0.f, c2 = 0.f, c3 = 0.f;
        #pragma unroll 4
        for (int s = 0; s < 48; s += 4) {
            c0 = fmaf(sSc[s],   sEnc[(s)*H + tid],   c0);
            c1 = fmaf(sSc[s+1], sEnc[(s+1)*H + tid], c1);
            c2 = fmaf(sSc[s+2], sEnc[(s+2)*H + tid], c2);
            c3 = fmaf(sSc[s+3], sEnc[(s+3)*H + tid], c3);
        }
        c0 = fmaf(sSc[48], sEnc[48*H + tid], c0);
        c1 = fmaf(sSc[49], sEnc[49*H + tid], c1);
        g_pctx[(b*NCH + c)*H + tid] = (c0 + c1) + (c2 + c3);
    }
}

// ---------------- C: combine partials + att_dist + dec_h + p_gen -------------
__global__ __launch_bounds__(256) void k_comb_att(
    const float* __restrict__ outhw, const float* __restrict__ outhb,
    const float* __restrict__ genw,  const float* __restrict__ genb,
    float* __restrict__ out) {
    __shared__ __align__(16) float dctx[2*H];
    __shared__ float red[256];
    __shared__ float sW[NCH];
    int b = blockIdx.x, tid = threadIdx.x;

    if (tid == 0) {
        float m[NCH], sm = -1e30f;
        #pragma unroll
        for (int c = 0; c < NCH; c++) { m[c] = g_cmax[b*NCH + c]; sm = fmaxf(sm, m[c]); }
        float L = 0.f;
        #pragma unroll
        for (int c = 0; c < NCH; c++) L += g_csum[b*NCH + c]*__expf(m[c] - sm);
        float invL = 1.f/L;
        #pragma unroll
        for (int c = 0; c < NCH; c++) sW[c] = __expf(m[c] - sm)*invL;
    }
    __syncthreads();

    for (int i = tid; i < S; i += 256) {
        float a = g_esc[b*S + i]*sW[i/CH];
        g_ad[b*S + i] = a;
        out[OUT_ATT + b*S + i] = a;
    }

    {
        float ctx = 0.f;
        #pragma unroll
        for (int c = 0; c < NCH; c++) ctx = fmaf(g_pctx[(b*NCH + c)*H + tid], sW[c], ctx);
        dctx[H + tid] = ctx;
    }
    dctx[tid] = g_hnew[b*H + tid];
    __syncthreads();

    // dec_h GEMV: warp per e-row, float4 hoisted loads, 4-way chains
    int warp = tid >> 5, lane = tid & 31;
    {
        const float4* dc4 = (const float4*)dctx;
        float4 d0 = dc4[lane], d1 = dc4[lane+32], d2 = dc4[lane+64], d3 = dc4[lane+96];
        #pragma unroll 2
        for (int i = 0; i < 16; i++) {
            int e = warp*16 + i;
            const float4* wr = (const float4*)(outhw + (size_t)e*H2);
            float4 w0 = wr[lane], w1 = wr[lane+32], w2 = wr[lane+64], w3 = wr[lane+96];
            float s0 = fmaf(w0.w, d0.w, fmaf(w0.z, d0.z, fmaf(w0.y, d0.y, w0.x*d0.x)));
            float s1 = fmaf(w1.w, d1.w, fmaf(w1.z, d1.z, fmaf(w1.y, d1.y, w1.x*d1.x)));
            float s2 = fmaf(w2.w, d2.w, fmaf(w2.z, d2.z, fmaf(w2.y, d2.y, w2.x*d2.x)));
            float s3 = fmaf(w3.w, d3.w, fmaf(w3.z, d3.z, fmaf(w3.y, d3.y, w3.x*d3.x)));
            float a = (s0 + s1) + (s2 + s3);
            #pragma unroll
            for (int o = 16; o; o >>= 1) a += __shfl_xor_sync(0xffffffffu, a, o);
            if (lane == 0) g_decH[b*E + e] = a + outhb[e];
        }
    }

    float p = 0.f;
    for (int i = tid; i < 2*H + E; i += 256) {
        float cv = (i < 2*H) ? dctx[i] : g_x[b*E + (i - 2*H)];
        p = fmaf(cv, genw[i], p);
    }
    red[tid] = p; __syncthreads();
    for (int o = 128; o; o >>= 1) { if (tid < o) red[tid] += red[tid+o]; __syncthreads(); }
    if (tid == 0) {
        float pg = 1.f/(1.f + __expf(-(red[0] + genb[0])));
        g_pgen[b] = pg;
        out[OUT_PGEN + b] = pg;
    }
}

// ---------------- D: vocab GEMM via fp16 tensor-core single pass --------------
// logits = fp16(Wv) . fp16(dec_h), fp32 accum; rounding error ~2e-4 rel on p_vocab
extern __shared__ char smem_d[];
__global__ __launch_bounds__(256, 2) void k_logits(
    const float* __restrict__ Wv, const float* __restrict__ bv) {
    __half* sWh = (__half*)smem_d;
    __half* sDh = sWh + 128*WSTR;
    float* sC    = (float*)smem_d;                    // reused after MMA
    float* sBias = (float*)(smem_d + 2*128*WSTR*2);

    int tid = threadIdx.x;
    int v0 = blockIdx.x*128;
    bool full = (v0 + 128 <= V);

    if (full) {
        for (int i = tid; i < 128*32; i += 256) {
            int r = i >> 5, kq = i & 31;
            float4 w4 = *(const float4*)&Wv[(size_t)(v0 + r)*E + kq*4];
            __half2* ph = (__half2*)&sWh[r*WSTR + kq*4];
            ph[0] = __half2(__float2half(w4.x), __float2half(w4.y));
            ph[1] = __half2(__float2half(w4.z), __float2half(w4.w));
        }
    } else {
        for (int i = tid; i < 128*128; i += 256) {
            int r = i >> 7, k = i & 127;
            int v = v0 + r;
            float w = (v < V) ? Wv[(size_t)v*E + k] : 0.f;
            sWh[r*WSTR + k] = __float2half(w);
        }
    }
    for (int i = tid; i < 128*32; i += 256) {
        int bb = i >> 5, kq = i & 31;
        float4 d4 = *(const float4*)&g_decH[bb*E + kq*4];
        __half2* ph = (__half2*)&sDh[bb*WSTR + kq*4];
        ph[0] = __half2(__float2half(d4.x), __float2half(d4.y));
        ph[1] = __half2(__float2half(d4.z), __float2half(d4.w));
    }
    if (tid < 128) sBias[tid] = (v0 + tid < V) ? bv[v0 + tid] : 0.f;
    __syncthreads();

    int warp = tid >> 5, lane = tid & 31;
    int mBase = (warp & 3)*32;     // vocab offset in tile
    int nBase = (warp >> 2)*64;    // batch offset in tile

    float acc[2][8][4];
    #pragma unroll
    for (int mi = 0; mi < 2; mi++)
        #pragma unroll
        for (int j = 0; j < 8; j++)
            #pragma unroll
            for (int q = 0; q < 4; q++) acc[mi][j][q] = 0.f;

    int aRow = mBase + (lane & 7) + ((lane >> 3) & 1)*8;
    int aK   = (lane >> 4)*8;
    int bRow = nBase + (lane & 7) + (lane >> 4)*8;
    int bK   = ((lane >> 3) & 1)*8;

    uint32_t uWh = smem_u32(sWh) + (uint32_t)(aRow*WSTR + aK)*2;
    uint32_t uDh = smem_u32(sDh) + (uint32_t)(bRow*WSTR + bK)*2;

    #pragma unroll
    for (int k0 = 0; k0 < 128; k0 += 16) {
        uint32_t ah[2][4];
        #pragma unroll
        for (int mi = 0; mi < 2; mi++) {
            uint32_t adh = uWh + (uint32_t)(mi*16*WSTR + k0)*2;
            asm volatile("ldmatrix.sync.aligned.m8n8.x4.shared.b16 {%0,%1,%2,%3}, [%4];"
                : "=r"(ah[mi][0]), "=r"(ah[mi][1]), "=r"(ah[mi][2]), "=r"(ah[mi][3])
                : "r"(adh));
        }
        #pragma unroll
        for (int jp = 0; jp < 4; jp++) {
            uint32_t bfr[4];
            uint32_t bd = uDh + (uint32_t)(jp*16*WSTR + k0)*2;
            asm volatile("ldmatrix.sync.aligned.m8n8.x4.shared.b16 {%0,%1,%2,%3}, [%4];"
                : "=r"(bfr[0]), "=r"(bfr[1]), "=r"(bfr[2]), "=r"(bfr[3])
                : "r"(bd));
            #pragma unroll
            for (int mi = 0; mi < 2; mi++) {
                asm volatile(
                    "mma.sync.aligned.m16n8k16.row.col.f32.f16.f16.f32 "
                    "{%0,%1,%2,%3}, {%4,%5,%6,%7}, {%8,%9}, {%0,%1,%2,%3};"
                    : "+f"(acc[mi][2*jp][0]), "+f"(acc[mi][2*jp][1]),
                      "+f"(acc[mi][2*jp][2]), "+f"(acc[mi][2*jp][3])
                    : "r"(ah[mi][0]), "r"(ah[mi][1]), "r"(ah[mi][2]), "r"(ah[mi][3]),
                      "r"(bfr[0]), "r"(bfr[1]));
                asm volatile(
                    "mma.sync.aligned.m16n8k16.row.col.f32.f16.f16.f32 "
                    "{%0,%1,%2,%3}, {%4,%5,%6,%7}, {%8,%9}, {%0,%1,%2,%3};"
                    : "+f"(acc[mi][2*jp+1][0]), "+f"(acc[mi][2*jp+1][1]),
                      "+f"(acc[mi][2*jp+1][2]), "+f"(acc[mi][2*jp+1][3])
                    : "r"(ah[mi][0]), "r"(ah[mi][1]), "r"(ah[mi][2]), "r"(ah[mi][3]),
                      "r"(bfr[2]), "r"(bfr[3]));
            }
        }
    }

    __syncthreads();
    #pragma unroll
    for (int mi = 0; mi < 2; mi++)
        #pragma unroll
        for (int j = 0; j < 8; j++)
            #pragma unroll
            for (int q = 0; q < 4; q++) {
                int vl = mBase + 16*mi + (lane >> 2) + ((q >> 1) ? 8 : 0);
                int bl = nBase + 8*j + 2*(lane & 3) + (q & 1);
                sC[bl*VSTR + vl] = acc[mi][j][q];
            }
    __syncthreads();

    int nvalid = min(128, V - v0);
    for (int r = 0; r < 16; r++) {
        int bb = warp*16 + r;
        const float4 x4 = ((const float4*)(sC + bb*VSTR))[lane];
        int vl = lane*4;
        float val[4] = {x4.x + sBias[vl], x4.y + sBias[vl+1],
                        x4.z + sBias[vl+2], x4.w + sBias[vl+3]};
        float m = -1e30f;
        #pragma unroll
        for (int i = 0; i < 4; i++) if (vl + i < nvalid) m = fmaxf(m, val[i]);
        #pragma unroll
        for (int o = 16; o; o >>= 1) m = fmaxf(m, __shfl_xor_sync(0xffffffffu, m, o));
        float s = 0.f;
        #pragma unroll
        for (int i = 0; i < 4; i++) if (vl + i < nvalid) s += __expf(val[i] - m);
        #pragma unroll
        for (int o = 16; o; o >>= 1) s += __shfl_xor_sync(0xffffffffu, s, o);
        #pragma unroll
        for (int i = 0; i < 4; i++)
            if (vl + i < nvalid) g_logits[(size_t)bb*V + v0 + vl + i] = val[i];
        if (lane == 0) {
            g_pmax[bb*NBLK + blockIdx.x] = m;
            g_psum[bb*NBLK + blockIdx.x] = s;
        }
    }
}

// ---------------- D2: combine softmax partials (tiny) ------------------------
__global__ void k_comb() {
    __shared__ float sm[128], ss[128];
    int b = blockIdx.x, tid = threadIdx.x;
    float m = -1e30f, s = 0.f;
    for (int i = tid; i < NBLK; i += 128) {
        float pm = g_pmax[b*NBLK + i], ps = g_psum[b*NBLK + i];
        if (pm > m) { s = s*__expf(m - pm) + ps; m = pm; }
        else          s += ps*__expf(pm - m);
    }
    sm[tid] = m; ss[tid] = s; __syncthreads();
    for (int o = 64; o; o >>= 1) {
        if (tid < o) {
            float m1 = sm[tid], s1 = ss[tid];
            float m2 = sm[tid+o], s2 = ss[tid+o];
            float nm = fmaxf(m1, m2);
            sm[tid] = nm;
            ss[tid] = s1*__expf(m1 - nm) + s2*__expf(m2 - nm);
        }
        __syncthreads();
    }
    if (tid == 0) { g_rowmax[b] = sm[0]; g_rowinv[b] = 1.f/ss[0]; }
}

// ---------------- E: p_vocab + p_final (vectorized) ---------------------------
__global__ __launch_bounds__(256) void k_final(float* __restrict__ out) {
    int b = blockIdx.y;
    int v = (blockIdx.x*256 + threadIdx.x)*4;
    if (v >= VP) return;
    float pg = g_pgen[b];
    if (v < V) {
        float4 l = *(const float4*)&g_logits[(size_t)b*V + v];
        float mx = g_rowmax[b], inv = g_rowinv[b];
        float4 p;
        p.x = __expf(l.x - mx)*inv; p.y = __expf(l.y - mx)*inv;
        p.z = __expf(l.z - mx)*inv; p.w = __expf(l.w - mx)*inv;
        *(float4*)&out[OUT_PVOCAB + (size_t)b*V + v] = p;
        float2 f0 = make_float2(p.x*pg, p.y*pg);
        float2 f1 = make_float2(p.z*pg, p.w*pg);
        *(float2*)&out[OUT_PFINAL + (size_t)b*VP + v]     = f0;
        *(float2*)&out[OUT_PFINAL + (size_t)b*VP + v + 2] = f1;
    } else {
        #pragma unroll
        for (int i = 0; i < 4; i += 2)
            if (v + i < VP)
                *(float2*)&out[OUT_PFINAL + (size_t)b*VP + v + i] = make_float2(0.f, 0.f);
    }
}

// ---------------- F: pointer scatter ------------------------------------------
__global__ void k_scatter(const int* __restrict__ fiv, float* __restrict__ out) {
    int b = blockIdx.x;
    float w = 1.f - g_pgen[b];
    for (int s = threadIdx.x; s < S; s += blockDim.x) {
        int idx = fiv[b*S + s];
        atomicAdd(&out[OUT_PFINAL + (size_t)b*VP + idx], w*g_ad[b*S + s]);
    }
}

// ---------------- launcher ---------------------------------------------------
extern "C" void kernel_launch(void* const* d_in, const int* in_sizes, int n_in,
                              void* d_out, int out_size) {
    const int*   tok   = (const int*)  d_in[0];
    const float* hprev = (const float*)d_in[1];
    const float* enc   = (const float*)d_in[2];
    const int*   fiv   = (const int*)  d_in[3];
    const float* emb   = (const float*)d_in[4];
    const float* Wih   = (const float*)d_in[5];
    const float* Whh   = (const float*)d_in[6];
    const float* bih   = (const float*)d_in[7];
    const float* bhh   = (const float*)d_in[8];
    const float* wh    = (const float*)d_in[9];
    const float* ws    = (const float*)d_in[10];
    const float* ab    = (const float*)d_in[11];
    const float* av    = (const float*)d_in[12];
    const float* genw  = (const float*)d_in[13];
    const float* genb  = (const float*)d_in[14];
    const float* outhw = (const float*)d_in[15];
    const float* outhb = (const float*)d_in[16];
    const float* Wv    = (const float*)d_in[17];
    const float* bv    = (const float*)d_in[18];
    float* out = (float*)d_out;

    cudaFuncSetAttribute(k_logits, cudaFuncAttributeMaxDynamicSharedMemorySize, SMEM_D1);
    cudaFuncSetAttribute(k_part,   cudaFuncAttributeMaxDynamicSharedMemorySize, SMEM_P);

    k_gates   <<<dim3(12, 8), 256>>>(tok, emb, hprev, Wih, Whh, bih, bhh);
    k_gru     <<<B, H>>>(hprev, out);
    k_part    <<<dim3(NCH, B), 256, SMEM_P>>>(enc, wh, ws, ab, av);
    k_comb_att<<<B, 256>>>(outhw, outhb, genw, genb, out);
    k_logits  <<<NBLK, 256, SMEM_D1>>>(Wv, bv);
    k_comb    <<<B, 128>>>();
    k_final   <<<dim3((VP + 1023)/1024, B), 256>>>(out);
    k_scatter <<<B, 256>>>(fiv, out);
}

// round 7
// speedup vs baseline: 1.7035x; 1.1583x over previous
#include <cuda_runtime.h>
#include <cuda_fp16.h>
#include <cstdint>

#define B 128
#define S 400
#define H 256
#define E 128
#define V 50000
#define PAD 250
#define VP 50250
#define H2 512
#define H3 768
#define NBLK 391            // ceil(V/128)
#define WSTR 136            // fp16 elems per smem row (bank-conflict-free ldmatrix)
#define CH 50               // seq rows per attention chunk
#define NCH 8               // chunks per batch row (CH*NCH == S)

// Output layout: concat of flattened (h_new, p_final, p_gen, p_vocab, att_dist)
#define OUT_HNEW   0
#define OUT_PFINAL (B*H)
#define OUT_PGEN   (OUT_PFINAL + B*VP)
#define OUT_PVOCAB (OUT_PGEN + B)
#define OUT_ATT    (OUT_PVOCAB + B*V)

#define SMEM_D1 (2*128*WSTR*2 + 128*4)          // Wh, Dh fp16 tiles + bias row
#define SMEM_P  ((CH*H + 3*H + 64)*4)           // enc chunk + wh/av/ch + scores

// ---------------- scratch (static device globals; no allocation) -------------
__device__ float g_x[B*E];
__device__ float g_hnew[B*H];
__device__ float g_gsum[B*H3];
__device__ float g_ghn[B*H];
__device__ float g_esc[B*S];         // exp(score - m_chunk)
__device__ float g_cmax[B*NCH];
__device__ float g_csum[B*NCH];
__device__ float g_pctx[B*NCH*H];    // partial contexts
__device__ float g_ad[B*S];
__device__ float g_decH[B*E];        // [b][e] fp32
__device__ float g_logits[B*V];      // 25.6 MB
__device__ float g_pmax[B*NBLK];
__device__ float g_psum[B*NBLK];
__device__ float g_rowmax[B];
__device__ float g_rowinv[B];
__device__ float g_pgen[B];

__device__ __forceinline__ float tanh_hw(float x) {
    float y;
    asm("tanh.approx.f32 %0, %1;" : "=f"(y) : "f"(x));
    return y;
}

__device__ __forceinline__ uint32_t smem_u32(const void* p) {
    return (uint32_t)__cvta_generic_to_shared(p);
}

// ---------------- A1: GRU gate GEMMs (embedding gather fused in) -------------
__global__ __launch_bounds__(256) void k_gates(
    const int* __restrict__ tok,    const float* __restrict__ emb,
    const float* __restrict__ hprev, const float* __restrict__ Wih,
    const float* __restrict__ Whh,  const float* __restrict__ bih,
    const float* __restrict__ bhh) {
    __shared__ float xhT[384*20];
    __shared__ float wT[64*65];
    __shared__ int   s_tok[16];
    int j0 = blockIdx.x*64, b0 = blockIdx.y*16;
    int tid = threadIdx.x;

    if (tid < 16) s_tok[tid] = tok[b0 + tid];
    __syncthreads();

    for (int i = tid; i < 16*384; i += 256) {
        int bl = i/384, k = i%384;
        float v = (k < 128) ? emb[(size_t)s_tok[bl]*E + k] : hprev[(b0+bl)*H + (k-128)];
        xhT[k*20 + bl] = v;
        if (blockIdx.x == 0 && k < 128) g_x[(b0+bl)*E + k] = v;
    }

    int j_loc = tid & 63, bq = tid >> 6;
    int j = j0 + j_loc;
    bool isN = (j >= 2*H);
    float acc[4]  = {0.f,0.f,0.f,0.f};
    float accn[4] = {0.f,0.f,0.f,0.f};

    for (int kt = 0; kt < 384; kt += 64) {
        __syncthreads();
        for (int i = tid; i < 64*64; i += 256) {
            int jl = i >> 6, kk = i & 63;
            int k = kt + kk, jj = j0 + jl;
            float w = (k < 128) ? Wih[(size_t)jj*E + k] : Whh[(size_t)jj*H + (k-128)];
            wT[kk*65 + jl] = w;
        }
        __syncthreads();
        if (kt < 128) {
            #pragma unroll 8
            for (int kk = 0; kk < 64; kk++) {
                float w = wT[kk*65 + j_loc];
                float4 xv = *(const float4*)&xhT[(kt+kk)*20 + bq*4];
                acc[0] = fmaf(w, xv.x, acc[0]); acc[1] = fmaf(w, xv.y, acc[1]);
                acc[2] = fmaf(w, xv.z, acc[2]); acc[3] = fmaf(w, xv.w, acc[3]);
            }
        } else {
            #pragma unroll 8
            for (int kk = 0; kk < 64; kk++) {
                float w = wT[kk*65 + j_loc];
                float4 xv = *(const float4*)&xhT[(kt+kk)*20 + bq*4];
                acc[0] = fmaf(w, xv.x, acc[0]); acc[1] = fmaf(w, xv.y, acc[1]);
                acc[2] = fmaf(w, xv.z, acc[2]); acc[3] = fmaf(w, xv.w, acc[3]);
                accn[0] = fmaf(w, xv.x, accn[0]); accn[1] = fmaf(w, xv.y, accn[1]);
                accn[2] = fmaf(w, xv.z, accn[2]); accn[3] = fmaf(w, xv.w, accn[3]);
            }
        }
    }
    float bs = bih[j] + bhh[j];
    #pragma unroll
    for (int i = 0; i < 4; i++) {
        int b = b0 + bq*4 + i;
        g_gsum[b*H3 + j] = acc[i] + bs;
        if (isN) g_ghn[b*H + (j - 2*H)] = accn[i] + bhh[j];
    }
}

// ---------------- A2: GRU elementwise (precise: h_new dominates out norm) ----
__global__ void k_gru(const float* __restrict__ hprev, float* __restrict__ out) {
    int b = blockIdx.x, j = threadIdx.x;
    float gr = g_gsum[b*H3 + j];
    float gz = g_gsum[b*H3 + H + j];
    float gn = g_gsum[b*H3 + 2*H + j];
    float hn = g_ghn[b*H + j];
    float r = 1.f/(1.f + __expf(-gr));
    float z = 1.f/(1.f + __expf(-gz));
    float n = tanhf(gn + (r - 1.f)*hn);
    float h = (1.f - z)*n + z*hprev[b*H + j];
    g_hnew[b*H + j] = h;
    out[OUT_HNEW + b*H + j] = h;
}

// ---------------- B: fused scores + chunk softmax + partial context ----------
extern __shared__ float smem_p[];
__global__ __launch_bounds__(256) void k_part(
    const float* __restrict__ enc, const float* __restrict__ wh,
    const float* __restrict__ ws,  const float* __restrict__ ab,
    const float* __restrict__ av) {
    float* sEnc = smem_p;               // [CH][H]
    float* s_wh = sEnc + CH*H;
    float* s_av = s_wh + H;
    float* s_ch = s_av + H;
    float* sSc  = s_ch + H;             // [CH] scores then exp values

    int c = blockIdx.x, b = blockIdx.y;
    int tid = threadIdx.x;
    int warp = tid >> 5, lane = tid & 31;

    s_wh[tid] = wh[tid];
    s_av[tid] = av[tid];
    s_ch[tid] = fmaf(ws[tid], g_hnew[b*H + tid], ab[0]);

    {
        const float4* src = (const float4*)(enc + ((size_t)b*S + c*CH)*H);
        float4* dst = (float4*)sEnc;
        #pragma unroll
        for (int i = tid; i < CH*H/4; i += 256) dst[i] = src[i];
    }
    __syncthreads();

    for (int s = warp; s < CH; s += 8) {
        const float* ep = sEnc + s*H;
        int h0 = lane*4;
        float acc = 0.f;
        float4 e0 = *(const float4*)&ep[h0];
        float4 w0 = *(const float4*)&s_wh[h0];
        float4 c0 = *(const float4*)&s_ch[h0];
        float4 a0 = *(const float4*)&s_av[h0];
        acc = fmaf(tanh_hw(fmaf(w0.x, e0.x, c0.x)), a0.x, acc);
        acc = fmaf(tanh_hw(fmaf(w0.y, e0.y, c0.y)), a0.y, acc);
        acc = fmaf(tanh_hw(fmaf(w0.z, e0.z, c0.z)), a0.z, acc);
        acc = fmaf(tanh_hw(fmaf(w0.w, e0.w, c0.w)), a0.w, acc);
        float4 e1 = *(const float4*)&ep[h0 + 128];
        float4 w1 = *(const float4*)&s_wh[h0 + 128];
        float4 c1 = *(const float4*)&s_ch[h0 + 128];
        float4 a1 = *(const float4*)&s_av[h0 + 128];
        acc = fmaf(tanh_hw(fmaf(w1.x, e1.x, c1.x)), a1.x, acc);
        acc = fmaf(tanh_hw(fmaf(w1.y, e1.y, c1.y)), a1.y, acc);
        acc = fmaf(tanh_hw(fmaf(w1.z, e1.z, c1.z)), a1.z, acc);
        acc = fmaf(tanh_hw(fmaf(w1.w, e1.w, c1.w)), a1.w, acc);
        #pragma unroll
        for (int o = 16; o; o >>= 1) acc += __shfl_xor_sync(0xffffffffu, acc, o);
        if (lane == 0) sSc[s] = acc;
    }
    __syncthreads();

    if (warp == 0) {
        float v0 = (lane      < CH) ? sSc[lane]      : -1e30f;
        float v1 = (lane + 32 < CH) ? sSc[lane + 32] : -1e30f;
        float m = fmaxf(v0, v1);
        #pragma unroll
        for (int o = 16; o; o >>= 1) m = fmaxf(m, __shfl_xor_sync(0xffffffffu, m, o));
        float e0 = (lane      < CH) ? __expf(v0 - m) : 0.f;
        float e1 = (lane + 32 < CH) ? __expf(v1 - m) : 0.f;
        if (lane      < CH) { sSc[lane]      = e0; g_esc[b*S + c*CH + lane]      = e0; }
        if (lane + 32 < CH) { sSc[lane + 32] = e1; g_esc[b*S + c*CH + lane + 32] = e1; }
        float s = e0 + e1;
        #pragma unroll
        for (int o = 16; o; o >>= 1) s += __shfl_xor_sync(0xffffffffu, s, o);
        if (lane == 0) { g_cmax[b*NCH + c] = m; g_csum[b*NCH + c] = s; }
    }
    __syncthreads();

    {
        float c0 = 0.f, c1 = 0.f, c2 = 0.f, c3 = 0.f;
        #pragma unroll 4
        for (int s = 0; s < 48; s += 4) {
            c0 = fmaf(sSc[s],   sEnc[(s)*H + tid],   c0);
            c1 = fmaf(sSc[s+1], sEnc[(s+1)*H + tid], c1);
            c2 = fmaf(sSc[s+2], sEnc[(s+2)*H + tid], c2);
            c3 = fmaf(sSc[s+3], sEnc[(s+3)*H + tid], c3);
        }
        c0 = fmaf(sSc[48], sEnc[48*H + tid], c0);
        c1 = fmaf(sSc[49], sEnc[49*H + tid], c1);
        g_pctx[(b*NCH + c)*H + tid] = (c0 + c1) + (c2 + c3);
    }
}

// ---------------- C: combine partials + att_dist + dec_h + p_gen -------------
// grid (4, B). Each block computes dctx (cheap) and a 32-row GEMV slice;
// block ez==0 additionally emits att_dist and p_gen.
__global__ __launch_bounds__(256) void k_comb_att(
    const float* __restrict__ outhw, const float* __restrict__ outhb,
    const float* __restrict__ genw,  const float* __restrict__ genb,
    float* __restrict__ out) {
    __shared__ __align__(16) float dctx[2*H];
    __shared__ float red[256];
    __shared__ float sW[NCH];
    int ez = blockIdx.x, b = blockIdx.y;
    int tid = threadIdx.x;
    int warp = tid >> 5, lane = tid & 31;

    if (warp == 0) {
        float m = (lane < NCH) ? g_cmax[b*NCH + lane] : -1e30f;
        float s = (lane < NCH) ? g_csum[b*NCH + lane] : 0.f;
        float sm = m;
        #pragma unroll
        for (int o = 16; o; o >>= 1) sm = fmaxf(sm, __shfl_xor_sync(0xffffffffu, sm, o));
        float t = s*__expf(m - sm);
        float L = t;
        #pragma unroll
        for (int o = 16; o; o >>= 1) L += __shfl_xor_sync(0xffffffffu, L, o);
        if (lane < NCH) sW[lane] = __expf(m - sm)/L;
    }
    __syncthreads();

    {
        float ctx = 0.f;
        #pragma unroll
        for (int c = 0; c < NCH; c++) ctx = fmaf(g_pctx[(b*NCH + c)*H + tid], sW[c], ctx);
        dctx[H + tid] = ctx;
        dctx[tid] = g_hnew[b*H + tid];
    }
    __syncthreads();

    // dec_h GEMV slice: e in [ez*32, ez*32+32), 4 rows per warp
    {
        const float4* dc4 = (const float4*)dctx;
        float4 d0 = dc4[lane], d1 = dc4[lane+32], d2 = dc4[lane+64], d3 = dc4[lane+96];
        #pragma unroll
        for (int i = 0; i < 4; i++) {
            int e = ez*32 + warp*4 + i;
            const float4* wr = (const float4*)(outhw + (size_t)e*H2);
            float4 w0 = wr[lane], w1 = wr[lane+32], w2 = wr[lane+64], w3 = wr[lane+96];
            float s0 = fmaf(w0.w, d0.w, fmaf(w0.z, d0.z, fmaf(w0.y, d0.y, w0.x*d0.x)));
            float s1 = fmaf(w1.w, d1.w, fmaf(w1.z, d1.z, fmaf(w1.y, d1.y, w1.x*d1.x)));
            float s2 = fmaf(w2.w, d2.w, fmaf(w2.z, d2.z, fmaf(w2.y, d2.y, w2.x*d2.x)));
            float s3 = fmaf(w3.w, d3.w, fmaf(w3.z, d3.z, fmaf(w3.y, d3.y, w3.x*d3.x)));
            float a = (s0 + s1) + (s2 + s3);
            #pragma unroll
            for (int o = 16; o; o >>= 1) a += __shfl_xor_sync(0xffffffffu, a, o);
            if (lane == 0) g_decH[b*E + e] = a + outhb[e];
        }
    }

    if (ez == 0) {
        for (int i = tid; i < S; i += 256) {
            float a = g_esc[b*S + i]*sW[i/CH];
            g_ad[b*S + i] = a;
            out[OUT_ATT + b*S + i] = a;
        }
        float p = 0.f;
        for (int i = tid; i < 2*H + E; i += 256) {
            float cv = (i < 2*H) ? dctx[i] : g_x[b*E + (i - 2*H)];
            p = fmaf(cv, genw[i], p);
        }
        red[tid] = p; __syncthreads();
        for (int o = 128; o; o >>= 1) { if (tid < o) red[tid] += red[tid+o]; __syncthreads(); }
        if (tid == 0) {
            float pg = 1.f/(1.f + __expf(-(red[0] + genb[0])));
            g_pgen[b] = pg;
            out[OUT_PGEN + b] = pg;
        }
    }
}

// ---------------- D: vocab GEMM, fp16 tensor core, direct-STG epilogue -------
extern __shared__ char smem_d[];
__global__ __launch_bounds__(256, 2) void k_logits(
    const float* __restrict__ Wv, const float* __restrict__ bv) {
    __half* sWh = (__half*)smem_d;
    __half* sDh = sWh + 128*WSTR;
    float* sBias = (float*)(smem_d + 2*128*WSTR*2);
    __shared__ float2 sPart[8][64];   // per-warp per-b (max, sum) partials

    int tid = threadIdx.x;
    int v0 = blockIdx.x*128;
    bool full = (v0 + 128 <= V);

    if (full) {
        for (int i = tid; i < 128*32; i += 256) {
            int r = i >> 5, kq = i & 31;
            float4 w4 = *(const float4*)&Wv[(size_t)(v0 + r)*E + kq*4];
            __half2* ph = (__half2*)&sWh[r*WSTR + kq*4];
            ph[0] = __half2(__float2half(w4.x), __float2half(w4.y));
            ph[1] = __half2(__float2half(w4.z), __float2half(w4.w));
        }
    } else {
        for (int i = tid; i < 128*128; i += 256) {
            int r = i >> 7, k = i & 127;
            int v = v0 + r;
            float w = (v < V) ? Wv[(size_t)v*E + k] : 0.f;
            sWh[r*WSTR + k] = __float2half(w);
        }
    }
    for (int i = tid; i < 128*32; i += 256) {
        int bb = i >> 5, kq = i & 31;
        float4 d4 = *(const float4*)&g_decH[bb*E + kq*4];
        __half2* ph = (__half2*)&sDh[bb*WSTR + kq*4];
        ph[0] = __half2(__float2half(d4.x), __float2half(d4.y));
        ph[1] = __half2(__float2half(d4.z), __float2half(d4.w));
    }
    if (tid < 128) sBias[tid] = (v0 + tid < V) ? bv[v0 + tid] : 0.f;
    __syncthreads();

    int warp = tid >> 5, lane = tid & 31;
    int mBase = (warp & 3)*32;     // vocab offset in tile
    int nBase = (warp >> 2)*64;    // batch offset in tile

    float acc[2][8][4];
    #pragma unroll
    for (int mi = 0; mi < 2; mi++)
        #pragma unroll
        for (int j = 0; j < 8; j++)
            #pragma unroll
            for (int q = 0; q < 4; q++) acc[mi][j][q] = 0.f;

    int aRow = mBase + (lane & 7) + ((lane >> 3) & 1)*8;
    int aK   = (lane >> 4)*8;
    int bRow = nBase + (lane & 7) + (lane >> 4)*8;
    int bK   = ((lane >> 3) & 1)*8;

    uint32_t uWh = smem_u32(sWh) + (uint32_t)(aRow*WSTR + aK)*2;
    uint32_t uDh = smem_u32(sDh) + (uint32_t)(bRow*WSTR + bK)*2;

    #pragma unroll
    for (int k0 = 0; k0 < 128; k0 += 16) {
        uint32_t ah[2][4];
        #pragma unroll
        for (int mi = 0; mi < 2; mi++) {
            uint32_t adh = uWh + (uint32_t)(mi*16*WSTR + k0)*2;
            asm volatile("ldmatrix.sync.aligned.m8n8.x4.shared.b16 {%0,%1,%2,%3}, [%4];"
                : "=r"(ah[mi][0]), "=r"(ah[mi][1]), "=r"(ah[mi][2]), "=r"(ah[mi][3])
                : "r"(adh));
        }
        #pragma unroll
        for (int jp = 0; jp < 4; jp++) {
            uint32_t bfr[4];
            uint32_t bd = uDh + (uint32_t)(jp*16*WSTR + k0)*2;
            asm volatile("ldmatrix.sync.aligned.m8n8.x4.shared.b16 {%0,%1,%2,%3}, [%4];"
                : "=r"(bfr[0]), "=r"(bfr[1]), "=r"(bfr[2]), "=r"(bfr[3])
                : "r"(bd));
            #pragma unroll
            for (int mi = 0; mi < 2; mi++) {
                asm volatile(
                    "mma.sync.aligned.m16n8k16.row.col.f32.f16.f16.f32 "
                    "{%0,%1,%2,%3}, {%4,%5,%6,%7}, {%8,%9}, {%0,%1,%2,%3};"
                    : "+f"(acc[mi][2*jp][0]), "+f"(acc[mi][2*jp][1]),
                      "+f"(acc[mi][2*jp][2]), "+f"(acc[mi][2*jp][3])
                    : "r"(ah[mi][0]), "r"(ah[mi][1]), "r"(ah[mi][2]), "r"(ah[mi][3]),
                      "r"(bfr[0]), "r"(bfr[1]));
                asm volatile(
                    "mma.sync.aligned.m16n8k16.row.col.f32.f16.f16.f32 "
                    "{%0,%1,%2,%3}, {%4,%5,%6,%7}, {%8,%9}, {%0,%1,%2,%3};"
                    : "+f"(acc[mi][2*jp+1][0]), "+f"(acc[mi][2*jp+1][1]),
                      "+f"(acc[mi][2*jp+1][2]), "+f"(acc[mi][2*jp+1][3])
                    : "r"(ah[mi][0]), "r"(ah[mi][1]), "r"(ah[mi][2]), "r"(ah[mi][3]),
                      "r"(bfr[2]), "r"(bfr[3]));
            }
        }
    }

    // direct epilogue: bias add + STG (32B segments) + in-register partials
    int nvalid = min(128, V - v0);
    float bias_v[2][2];
    #pragma unroll
    for (int mi = 0; mi < 2; mi++)
        #pragma unroll
        for (int qh = 0; qh < 2; qh++)
            bias_v[mi][qh] = sBias[mBase + 16*mi + (lane >> 2) + 8*qh];

    #pragma unroll
    for (int mi = 0; mi < 2; mi++)
        #pragma unroll
        for (int j = 0; j < 8; j++)
            #pragma unroll
            for (int q = 0; q < 4; q++) {
                float val = acc[mi][j][q] + bias_v[mi][q >> 1];
                int vl = mBase + 16*mi + (lane >> 2) + 8*(q >> 1);
                int bb = nBase + 8*j + 2*(lane & 3) + (q & 1);
                if (vl < nvalid) g_logits[(size_t)bb*V + v0 + vl] = val;
                else             val = -1e30f;
                acc[mi][j][q] = val;
            }

    // per-warp per-b (max, sumexp) over this warp's 32 v-rows
    #pragma unroll
    for (int j = 0; j < 8; j++)
        #pragma unroll
        for (int ql = 0; ql < 2; ql++) {
            float m = fmaxf(fmaxf(acc[0][j][ql], acc[0][j][ql+2]),
                            fmaxf(acc[1][j][ql], acc[1][j][ql+2]));
            #pragma unroll
            for (int o = 4; o <= 16; o <<= 1) m = fmaxf(m, __shfl_xor_sync(0xffffffffu, m, o));
            float s = __expf(acc[0][j][ql] - m) + __expf(acc[0][j][ql+2] - m)
                    + __expf(acc[1][j][ql] - m) + __expf(acc[1][j][ql+2] - m);
            #pragma unroll
            for (int o = 4; o <= 16; o <<= 1) s += __shfl_xor_sync(0xffffffffu, s, o);
            if ((lane >> 2) == 0)
                sPart[warp][8*j + 2*(lane & 3) + ql] = make_float2(m, s);
        }
    __syncthreads();

    if (tid < 128) {
        int wg = tid >> 6, bl = tid & 63;
        float2 p0 = sPart[wg*4 + 0][bl], p1 = sPart[wg*4 + 1][bl];
        float2 p2 = sPart[wg*4 + 2][bl], p3 = sPart[wg*4 + 3][bl];
        float m = fmaxf(fmaxf(p0.x, p1.x), fmaxf(p2.x, p3.x));
        float s = p0.y*__expf(p0.x - m) + p1.y*__expf(p1.x - m)
                + p2.y*__expf(p2.x - m) + p3.y*__expf(p3.x - m);
        g_pmax[tid*NBLK + blockIdx.x] = m;
        g_psum[tid*NBLK + blockIdx.x] = s;
    }
}

// ---------------- D2: combine softmax partials (tiny) ------------------------
__global__ void k_comb() {
    __shared__ float sm[128], ss[128];
    int b = blockIdx.x, tid = threadIdx.x;
    float m = -1e30f, s = 0.f;
    for (int i = tid; i < NBLK; i += 128) {
        float pm = g_pmax[b*NBLK + i], ps = g_psum[b*NBLK + i];
        if (pm > m) { s = s*__expf(m - pm) + ps; m = pm; }
        else          s += ps*__expf(pm - m);
    }
    sm[tid] = m; ss[tid] = s; __syncthreads();
    for (int o = 64; o; o >>= 1) {
        if (tid < o) {
            float m1 = sm[tid], s1 = ss[tid];
            float m2 = sm[tid+o], s2 = ss[tid+o];
            float nm = fmaxf(m1, m2);
            sm[tid] = nm;
            ss[tid] = s1*__expf(m1 - nm) + s2*__expf(m2 - nm);
        }
        __syncthreads();
    }
    if (tid == 0) { g_rowmax[b] = sm[0]; g_rowinv[b] = 1.f/ss[0]; }
}

// ---------------- E: p_vocab + p_final (vectorized) ---------------------------
__global__ __launch_bounds__(256) void k_final(float* __restrict__ out) {
    int b = blockIdx.y;
    int v = (blockIdx.x*256 + threadIdx.x)*4;
    if (v >= VP) return;
    float pg = g_pgen[b];
    if (v < V) {
        float4 l = *(const float4*)&g_logits[(size_t)b*V + v];
        float mx = g_rowmax[b], inv = g_rowinv[b];
        float4 p;
        p.x = __expf(l.x - mx)*inv; p.y = __expf(l.y - mx)*inv;
        p.z = __expf(l.z - mx)*inv; p.w = __expf(l.w - mx)*inv;
        *(float4*)&out[OUT_PVOCAB + (size_t)b*V + v] = p;
        float2 f0 = make_float2(p.x*pg, p.y*pg);
        float2 f1 = make_float2(p.z*pg, p.w*pg);
        *(float2*)&out[OUT_PFINAL + (size_t)b*VP + v]     = f0;
        *(float2*)&out[OUT_PFINAL + (size_t)b*VP + v + 2] = f1;
    } else {
        #pragma unroll
        for (int i = 0; i < 4; i += 2)
            if (v + i < VP)
                *(float2*)&out[OUT_PFINAL + (size_t)b*VP + v + i] = make_float2(0.f, 0.f);
    }
}

// ---------------- F: pointer scatter ------------------------------------------
__global__ void k_scatter(const int* __restrict__ fiv, float* __restrict__ out) {
    int b = blockIdx.x;
    float w = 1.f - g_pgen[b];
    for (int s = threadIdx.x; s < S; s += blockDim.x) {
        int idx = fiv[b*S + s];
        atomicAdd(&out[OUT_PFINAL + (size_t)b*VP + idx], w*g_ad[b*S + s]);
    }
}

// ---------------- launcher ---------------------------------------------------
extern "C" void kernel_launch(void* const* d_in, const int* in_sizes, int n_in,
                              void* d_out, int out_size) {
    const int*   tok   = (const int*)  d_in[0];
    const float* hprev = (const float*)d_in[1];
    const float* enc   = (const float*)d_in[2];
    const int*   fiv   = (const int*)  d_in[3];
    const float* emb   = (const float*)d_in[4];
    const float* Wih   = (const float*)d_in[5];
    const float* Whh   = (const float*)d_in[6];
    const float* bih   = (const float*)d_in[7];
    const float* bhh   = (const float*)d_in[8];
    const float* wh    = (const float*)d_in[9];
    const float* ws    = (const float*)d_in[10];
    const float* ab    = (const float*)d_in[11];
    const float* av    = (const float*)d_in[12];
    const float* genw  = (const float*)d_in[13];
    const float* genb  = (const float*)d_in[14];
    const float* outhw = (const float*)d_in[15];
    const float* outhb = (const float*)d_in[16];
    const float* Wv    = (const float*)d_in[17];
    const float* bv    = (const float*)d_in[18];
    float* out = (float*)d_out;

    cudaFuncSetAttribute(k_logits, cudaFuncAttributeMaxDynamicSharedMemorySize, SMEM_D1);
    cudaFuncSetAttribute(k_part,   cudaFuncAttributeMaxDynamicSharedMemorySize, SMEM_P);

    k_gates   <<<dim3(12, 8), 256>>>(tok, emb, hprev, Wih, Whh, bih, bhh);
    k_gru     <<<B, H>>>(hprev, out);
    k_part    <<<dim3(NCH, B), 256, SMEM_P>>>(enc, wh, ws, ab, av);
    k_comb_att<<<dim3(4, B), 256>>>(outhw, outhb, genw, genb, out);
    k_logits  <<<NBLK, 256, SMEM_D1>>>(Wv, bv);
    k_comb    <<<B, 128>>>();
    k_final   <<<dim3((VP + 1023)/1024, B), 256>>>(out);
    k_scatter <<<B, 256>>>(fiv, out);
}